// round 1
// baseline (speedup 1.0000x reference)
#include <cuda_runtime.h>
#include <cstdint>

// ---------------- problem constants ----------------
#define BATCHN  256
#define NTOK    196
#define DIMC    256
#define NHEAD   8
#define KDIM    32
#define VDIM    128
#define HPC     192            // per-head channels in h (q32 + k32 + v128)
#define HIDC    1536
#define DHC     1024
#define EPSV    1e-5f
#define SCALEV  0.17677669529663687f   // 32^{-1/2}
#define MROWS   (BATCHN * NTOK)        // 50176

#define KS_STRIDE 33           // padded k-row stride (kills 32-way LDS conflict)
#define S_STRIDE  200

// ---------------- scratch (device globals; no allocs allowed) ----------------
__device__ float g_Y[(size_t)MROWS * HIDC];     // h = x @ Wqkv^T   (308 MB)
__device__ float g_O[(size_t)MROWS * DHC];      // attention output (205 MB)
__device__ float g_psum[64 * HIDC];
__device__ float g_psq [64 * HIDC];
__device__ float g_A1[HIDC];
__device__ float g_B1[HIDC];
__device__ float g_A2[DIMC];
__device__ float g_B2[DIMC];

// ---------------- GEMM: C[M,N] = A[M,K] * B[N,K]^T (both row-major, K inner) ----
// 64x64 tile, 16-wide K steps, 256 threads, 4x4 register blocking.
__global__ void gemm_nt64(const float* __restrict__ A, const float* __restrict__ B,
                          float* __restrict__ C, int M, int N, int K)
{
    __shared__ float As[16][64];   // [k][m]
    __shared__ float Bs[16][64];   // [k][n]
    const int t  = threadIdx.x;
    const int tx = t & 15, ty = t >> 4;
    const int m0 = blockIdx.y * 64, n0 = blockIdx.x * 64;
    const int lr = t >> 2, lk = (t & 3) * 4;

    float acc[4][4] = {};

    for (int k0 = 0; k0 < K; k0 += 16) {
        float4 a4 = *(const float4*)&A[(size_t)(m0 + lr) * K + k0 + lk];
        float4 b4 = *(const float4*)&B[(size_t)(n0 + lr) * K + k0 + lk];
        As[lk + 0][lr] = a4.x; As[lk + 1][lr] = a4.y;
        As[lk + 2][lr] = a4.z; As[lk + 3][lr] = a4.w;
        Bs[lk + 0][lr] = b4.x; Bs[lk + 1][lr] = b4.y;
        Bs[lk + 2][lr] = b4.z; Bs[lk + 3][lr] = b4.w;
        __syncthreads();

#pragma unroll
        for (int k = 0; k < 16; ++k) {
            float4 av = *(const float4*)&As[k][ty * 4];
            float4 bv = *(const float4*)&Bs[k][tx * 4];
            float am[4] = {av.x, av.y, av.z, av.w};
            float bm[4] = {bv.x, bv.y, bv.z, bv.w};
#pragma unroll
            for (int i = 0; i < 4; ++i)
#pragma unroll
                for (int j = 0; j < 4; ++j)
                    acc[i][j] = fmaf(am[i], bm[j], acc[i][j]);
        }
        __syncthreads();
    }

#pragma unroll
    for (int i = 0; i < 4; ++i) {
        float4 o = {acc[i][0], acc[i][1], acc[i][2], acc[i][3]};
        *(float4*)&C[(size_t)(m0 + ty * 4 + i) * N + n0 + tx * 4] = o;
    }
}

// ---------------- BN stats: deterministic two-stage reduction -------------------
// stage 1: grid (C/128, 64), each block reduces 784 rows for 128 channels
__global__ void stats_partial(const float* __restrict__ X, int C)
{
    const int c  = blockIdx.x * 128 + threadIdx.x;
    const int r0 = blockIdx.y * 784;
    float s = 0.f, q = 0.f;
    const float* p = X + (size_t)r0 * C + c;
    for (int r = 0; r < 784; ++r) {
        float v = p[(size_t)r * C];
        s += v;
        q += v * v;
    }
    g_psum[blockIdx.y * C + c] = s;
    g_psq [blockIdx.y * C + c] = q;
}

// stage 2: fold 64 partials (fixed order -> deterministic), emit affine (a, b):
// norm(y) = y*a + b
__global__ void stats_finalize(const float* __restrict__ gam, const float* __restrict__ bet,
                               int C, int which)
{
    const int c = blockIdx.x * blockDim.x + threadIdx.x;
    if (c >= C) return;
    float s = 0.f, q = 0.f;
    for (int i = 0; i < 64; ++i) { s += g_psum[i * C + c]; q += g_psq[i * C + c]; }
    const float invM = 1.0f / (float)MROWS;
    const float mu   = s * invM;
    const float var  = q * invM - mu * mu;
    const float a    = gam[c] * rsqrtf(var + EPSV);
    const float bb   = bet[c] - mu * a;
    if (which == 0) { g_A1[c] = a; g_B1[c] = bb; }
    else            { g_A2[c] = a; g_B2[c] = bb; }
}

// ---------------- attention: one block per (batch, head) ------------------------
__device__ __forceinline__ float hswish(float x)
{
    return x * __saturatef((x + 3.0f) * (1.0f / 6.0f));
}

__global__ void attn_kernel(const float* __restrict__ bias_table,
                            const int*   __restrict__ idxs)
{
    extern __shared__ float sm[];
    float* qs   = sm;                        // NTOK * 32
    float* ks   = qs  + NTOK * KDIM;         // NTOK * 33 (padded)
    float* vs   = ks  + NTOK * KS_STRIDE;    // NTOK * 128
    float* brow = vs  + NTOK * VDIM;         // NTOK
    float* S    = brow + NTOK;               // 8 * 200
    float* sA   = S   + 8 * S_STRIDE;        // 192
    float* sB   = sA  + HPC;                 // 192

    const int b   = blockIdx.x;
    const int h   = blockIdx.y;
    const int tid = threadIdx.x;             // 256 threads

    if (tid < HPC)  { sA[tid] = g_A1[h * HPC + tid]; sB[tid] = g_B1[h * HPC + tid]; }
    if (tid < NTOK) { brow[tid] = bias_table[h * NTOK + tid]; }
    __syncthreads();

    // load + normalize q,k,v into shared
    const size_t base = (size_t)(b * NTOK) * HIDC + h * HPC;
    for (int i = tid; i < NTOK * KDIM; i += 256) {
        const int n = i >> 5, d = i & 31;
        const size_t rb = base + (size_t)n * HIDC;
        qs[n * KDIM + d]      = g_Y[rb + d]        * sA[d]        + sB[d];
        ks[n * KS_STRIDE + d] = g_Y[rb + KDIM + d] * sA[KDIM + d] + sB[KDIM + d];
    }
    for (int i = tid; i < NTOK * VDIM; i += 256) {
        const int n = i >> 7, d = i & 127;
        vs[n * VDIM + d] = g_Y[base + (size_t)n * HIDC + 2 * KDIM + d]
                           * sA[2 * KDIM + d] + sB[2 * KDIM + d];
    }
    __syncthreads();

    const int w = tid >> 5, lane = tid & 31;

    for (int i0 = 0; i0 < NTOK; i0 += 8) {
        int nrow = NTOK - i0; if (nrow > 8) nrow = 8;

        // scores for 8 query rows
        for (int idx = tid; idx < nrow * NTOK; idx += 256) {
            const int i  = idx / NTOK;
            const int j  = idx - i * NTOK;
            const int qi = i0 + i;
            const float* qp = qs + qi * KDIM;
            const float* kp = ks + j * KS_STRIDE;
            float s = 0.f;
#pragma unroll
            for (int d = 0; d < KDIM; ++d) s = fmaf(qp[d], kp[d], s);
            S[i * S_STRIDE + j] = s * SCALEV + brow[idxs[qi * NTOK + j]];
        }
        __syncthreads();

        // softmax: one warp per row
        if (w < nrow) {
            float m = -1e30f;
            for (int j = lane; j < NTOK; j += 32) m = fmaxf(m, S[w * S_STRIDE + j]);
#pragma unroll
            for (int o = 16; o; o >>= 1) m = fmaxf(m, __shfl_xor_sync(0xffffffffu, m, o));
            float sum = 0.f;
            for (int j = lane; j < NTOK; j += 32) {
                float e = __expf(S[w * S_STRIDE + j] - m);
                S[w * S_STRIDE + j] = e;
                sum += e;
            }
#pragma unroll
            for (int o = 16; o; o >>= 1) sum += __shfl_xor_sync(0xffffffffu, sum, o);
            const float inv = 1.0f / sum;
            for (int j = lane; j < NTOK; j += 32) S[w * S_STRIDE + j] *= inv;
        }
        __syncthreads();

        // O = P @ V, one warp per row, lane owns 4 consecutive v-channels
        if (w < nrow) {
            float4 acc = {0.f, 0.f, 0.f, 0.f};
            const float4* v4 = (const float4*)vs;
            const float*  Sp = S + w * S_STRIDE;
            for (int j = 0; j < NTOK; ++j) {
                const float p = Sp[j];
                const float4 v = v4[j * (VDIM / 4) + lane];
                acc.x = fmaf(p, v.x, acc.x);
                acc.y = fmaf(p, v.y, acc.y);
                acc.z = fmaf(p, v.z, acc.z);
                acc.w = fmaf(p, v.w, acc.w);
            }
            acc.x = hswish(acc.x); acc.y = hswish(acc.y);
            acc.z = hswish(acc.z); acc.w = hswish(acc.w);
            *(float4*)&g_O[(size_t)(b * NTOK + i0 + w) * DHC + h * VDIM + lane * 4] = acc;
        }
        __syncthreads();
    }
}

// ---------------- final BN apply (in place on d_out) ----------------------------
__global__ void norm2_kernel(float* __restrict__ Z)
{
    const size_t i = (size_t)blockIdx.x * 256 + threadIdx.x;   // float4 index
    float4 z = ((float4*)Z)[i];
    const int c4 = (int)(i & (DIMC / 4 - 1));
    const float4 a  = ((const float4*)g_A2)[c4];
    const float4 bb = ((const float4*)g_B2)[c4];
    z.x = fmaf(z.x, a.x, bb.x);
    z.y = fmaf(z.y, a.y, bb.y);
    z.z = fmaf(z.z, a.z, bb.z);
    z.w = fmaf(z.w, a.w, bb.w);
    ((float4*)Z)[i] = z;
}

// ---------------- launch ---------------------------------------------------------
static const size_t ATTN_SMEM_FLOATS =
    (size_t)NTOK * KDIM + (size_t)NTOK * KS_STRIDE + (size_t)NTOK * VDIM +
    NTOK + 8 * S_STRIDE + HPC + HPC;

extern "C" void kernel_launch(void* const* d_in, const int* in_sizes, int n_in,
                              void* d_out, int out_size)
{
    const float* x          = (const float*)d_in[0];
    const float* Wqkv       = (const float*)d_in[1];
    const float* g1         = (const float*)d_in[2];
    const float* b1         = (const float*)d_in[3];
    const float* bias_table = (const float*)d_in[4];
    const float* Wproj      = (const float*)d_in[5];
    const float* g2         = (const float*)d_in[6];
    const float* b2         = (const float*)d_in[7];
    const int*   idxs       = (const int*)d_in[8];
    float*       out        = (float*)d_out;

    float *Y, *O;
    cudaGetSymbolAddress((void**)&Y, g_Y);
    cudaGetSymbolAddress((void**)&O, g_O);

    const size_t attn_smem = ATTN_SMEM_FLOATS * sizeof(float);
    cudaFuncSetAttribute(attn_kernel, cudaFuncAttributeMaxDynamicSharedMemorySize,
                         (int)attn_smem);

    // 1) h = x @ Wqkv^T
    gemm_nt64<<<dim3(HIDC / 64, MROWS / 64), 256>>>(x, Wqkv, Y, MROWS, HIDC, DIMC);
    // 2) BN1 stats -> affine
    stats_partial<<<dim3(HIDC / 128, 64), 128>>>(Y, HIDC);
    stats_finalize<<<6, 256>>>(g1, b1, HIDC, 0);
    // 3) attention + hardswish
    attn_kernel<<<dim3(BATCHN, NHEAD), 256, attn_smem>>>(bias_table, idxs);
    // 4) Z = o @ Wproj^T  (into d_out)
    gemm_nt64<<<dim3(DIMC / 64, MROWS / 64), 256>>>(O, Wproj, out, MROWS, DIMC, DHC);
    // 5) BN2 stats -> affine
    stats_partial<<<dim3(DIMC / 128, 64), 128>>>(out, DIMC);
    stats_finalize<<<1, 256>>>(g2, b2, DIMC, 1);
    // 6) apply BN2 in place
    norm2_kernel<<<(MROWS * DIMC / 4) / 256, 256>>>(out);
}

// round 3
// speedup vs baseline: 1.3223x; 1.3223x over previous
#include <cuda_runtime.h>
#include <cstdint>

// ---------------- problem constants ----------------
#define BATCHN  256
#define NTOK    196
#define DIMC    256
#define NHEAD   8
#define KDIM    32
#define VDIM    128
#define HPC     192            // per-head channels in h (q32 + k32 + v128)
#define HIDC    1536
#define DHC     1024
#define EPSV    1e-5f
#define SCALEV  0.17677669529663687f   // 32^{-1/2}
#define MROWS   (BATCHN * NTOK)        // 50176

#define KS_STRIDE 33
#define S_STRIDE  200

// ---------------- scratch (device globals; no allocs allowed) ----------------
__device__ float g_Y[(size_t)MROWS * HIDC];     // h = x @ Wqkv^T   (308 MB)
__device__ float g_O[(size_t)MROWS * DHC];      // attention output (205 MB)
__device__ float g_psum[64 * HIDC];
__device__ float g_psq [64 * HIDC];
__device__ float g_A1[HIDC];
__device__ float g_B1[HIDC];
__device__ float g_A2[DIMC];
__device__ float g_B2[DIMC];

// ============================================================================
// TF32 tensor-core GEMM: C[M,N] = A[M,K] * B[N,K]^T  (row-major, K contiguous)
// Tile 128x128x16, 256 threads, warp grid 2(M) x 4(N), warp tile 64x32,
// mma.sync.m16n8k8.tf32. SMEM layout addr(k,x) = k*136 + ((k>>2)&3)*8 + x is
// conflict-free for both the STS transpose and all fragment LDS.
// ============================================================================

__device__ __forceinline__ unsigned f2tf(float f)
{
    unsigned u;
    asm("cvt.rna.tf32.f32 %0, %1;" : "=r"(u) : "f"(f));
    return u;
}

__device__ __forceinline__ int sw(int k, int x)
{
    return k * 136 + ((k >> 2) & 3) * 8 + x;
}

__device__ __forceinline__ void mma_tf32(float& d0, float& d1, float& d2, float& d3,
                                         unsigned a0, unsigned a1, unsigned a2, unsigned a3,
                                         unsigned b0, unsigned b1)
{
    asm volatile(
        "mma.sync.aligned.m16n8k8.row.col.f32.tf32.tf32.f32 "
        "{%0,%1,%2,%3}, {%4,%5,%6,%7}, {%8,%9}, {%0,%1,%2,%3};"
        : "+f"(d0), "+f"(d1), "+f"(d2), "+f"(d3)
        : "r"(a0), "r"(a1), "r"(a2), "r"(a3), "r"(b0), "r"(b1));
}

#define STG_WORDS 2208   // 16*136 + 24 + 128 rounded up

__global__ void __launch_bounds__(256, 2)
gemm_tf32(const float* __restrict__ A, const float* __restrict__ B,
          float* __restrict__ C, int M, int N, int K)
{
    __shared__ unsigned smA[2][STG_WORDS];
    __shared__ unsigned smB[2][STG_WORDS];

    const int t    = threadIdx.x;
    const int lane = t & 31;
    const int w    = t >> 5;
    const int g    = lane >> 2;      // 0..7
    const int tig  = lane & 3;       // 0..3
    const int wM   = w >> 2;         // 0..1
    const int wN   = w & 3;          // 0..3
    const int m0   = blockIdx.y * 128;
    const int n0   = blockIdx.x * 128;

    // staging assignment: thread loads rows (r, r+64), k-cols kc..kc+3
    const int r  = t >> 2;           // 0..63
    const int kc = (t & 3) * 4;      // 0,4,8,12

    const float* pA0 = A + (size_t)(m0 + r)      * K + kc;
    const float* pA1 = A + (size_t)(m0 + r + 64) * K + kc;
    const float* pB0 = B + (size_t)(n0 + r)      * K + kc;
    const float* pB1 = B + (size_t)(n0 + r + 64) * K + kc;

    float acc[4][4][4] = {};

    const int T = K / 16;

    // ---- prologue: stage tile 0 into buffer 0 ----
    {
        float4 va0 = *(const float4*)pA0;
        float4 va1 = *(const float4*)pA1;
        float4 vb0 = *(const float4*)pB0;
        float4 vb1 = *(const float4*)pB1;
        smA[0][sw(kc + 0, r)]      = f2tf(va0.x);
        smA[0][sw(kc + 1, r)]      = f2tf(va0.y);
        smA[0][sw(kc + 2, r)]      = f2tf(va0.z);
        smA[0][sw(kc + 3, r)]      = f2tf(va0.w);
        smA[0][sw(kc + 0, r + 64)] = f2tf(va1.x);
        smA[0][sw(kc + 1, r + 64)] = f2tf(va1.y);
        smA[0][sw(kc + 2, r + 64)] = f2tf(va1.z);
        smA[0][sw(kc + 3, r + 64)] = f2tf(va1.w);
        smB[0][sw(kc + 0, r)]      = f2tf(vb0.x);
        smB[0][sw(kc + 1, r)]      = f2tf(vb0.y);
        smB[0][sw(kc + 2, r)]      = f2tf(vb0.z);
        smB[0][sw(kc + 3, r)]      = f2tf(vb0.w);
        smB[0][sw(kc + 0, r + 64)] = f2tf(vb1.x);
        smB[0][sw(kc + 1, r + 64)] = f2tf(vb1.y);
        smB[0][sw(kc + 2, r + 64)] = f2tf(vb1.z);
        smB[0][sw(kc + 3, r + 64)] = f2tf(vb1.w);
    }
    __syncthreads();

    int buf = 0;
    for (int it = 0; it < T; ++it) {
        float4 va0, va1, vb0, vb1;
        const bool more = (it + 1) < T;
        if (more) {
            const int ko = (it + 1) * 16;
            va0 = *(const float4*)(pA0 + ko);
            va1 = *(const float4*)(pA1 + ko);
            vb0 = *(const float4*)(pB0 + ko);
            vb1 = *(const float4*)(pB1 + ko);
        }

        const unsigned* sA = smA[buf];
        const unsigned* sB = smB[buf];

#pragma unroll
        for (int kb = 0; kb < 16; kb += 8) {
            unsigned af[4][4];
            unsigned bfr[4][2];
#pragma unroll
            for (int ti = 0; ti < 4; ++ti) {
                const int m = wM * 64 + ti * 16 + g;
                af[ti][0] = sA[sw(kb + tig,     m)];
                af[ti][1] = sA[sw(kb + tig,     m + 8)];
                af[ti][2] = sA[sw(kb + tig + 4, m)];
                af[ti][3] = sA[sw(kb + tig + 4, m + 8)];
            }
#pragma unroll
            for (int tj = 0; tj < 4; ++tj) {
                const int n = wN * 32 + tj * 8 + g;
                bfr[tj][0] = sB[sw(kb + tig,     n)];
                bfr[tj][1] = sB[sw(kb + tig + 4, n)];
            }
#pragma unroll
            for (int ti = 0; ti < 4; ++ti)
#pragma unroll
                for (int tj = 0; tj < 4; ++tj)
                    mma_tf32(acc[ti][tj][0], acc[ti][tj][1], acc[ti][tj][2], acc[ti][tj][3],
                             af[ti][0], af[ti][1], af[ti][2], af[ti][3],
                             bfr[tj][0], bfr[tj][1]);
        }

        if (more) {
            const int nb = buf ^ 1;
            smA[nb][sw(kc + 0, r)]      = f2tf(va0.x);
            smA[nb][sw(kc + 1, r)]      = f2tf(va0.y);
            smA[nb][sw(kc + 2, r)]      = f2tf(va0.z);
            smA[nb][sw(kc + 3, r)]      = f2tf(va0.w);
            smA[nb][sw(kc + 0, r + 64)] = f2tf(va1.x);
            smA[nb][sw(kc + 1, r + 64)] = f2tf(va1.y);
            smA[nb][sw(kc + 2, r + 64)] = f2tf(va1.z);
            smA[nb][sw(kc + 3, r + 64)] = f2tf(va1.w);
            smB[nb][sw(kc + 0, r)]      = f2tf(vb0.x);
            smB[nb][sw(kc + 1, r)]      = f2tf(vb0.y);
            smB[nb][sw(kc + 2, r)]      = f2tf(vb0.z);
            smB[nb][sw(kc + 3, r)]      = f2tf(vb0.w);
            smB[nb][sw(kc + 0, r + 64)] = f2tf(vb1.x);
            smB[nb][sw(kc + 1, r + 64)] = f2tf(vb1.y);
            smB[nb][sw(kc + 2, r + 64)] = f2tf(vb1.z);
            smB[nb][sw(kc + 3, r + 64)] = f2tf(vb1.w);
        }
        __syncthreads();
        buf ^= 1;
    }

    // ---- epilogue ----
#pragma unroll
    for (int ti = 0; ti < 4; ++ti) {
#pragma unroll
        for (int tj = 0; tj < 4; ++tj) {
            const int row = m0 + wM * 64 + ti * 16 + g;
            const int col = n0 + wN * 32 + tj * 8 + 2 * tig;
            float2 lo = {acc[ti][tj][0], acc[ti][tj][1]};
            float2 hi = {acc[ti][tj][2], acc[ti][tj][3]};
            *(float2*)&C[(size_t)row * N + col]       = lo;
            *(float2*)&C[(size_t)(row + 8) * N + col] = hi;
        }
    }
}

// ---------------- BN stats: deterministic two-stage reduction -------------------
__global__ void stats_partial(const float* __restrict__ X, int C)
{
    const int c  = blockIdx.x * 128 + threadIdx.x;
    const int r0 = blockIdx.y * 784;
    float s = 0.f, q = 0.f;
    const float* p = X + (size_t)r0 * C + c;
    for (int r = 0; r < 784; ++r) {
        float v = p[(size_t)r * C];
        s += v;
        q += v * v;
    }
    g_psum[blockIdx.y * C + c] = s;
    g_psq [blockIdx.y * C + c] = q;
}

__global__ void stats_finalize(const float* __restrict__ gam, const float* __restrict__ bet,
                               int C, int which)
{
    const int c = blockIdx.x * blockDim.x + threadIdx.x;
    if (c >= C) return;
    float s = 0.f, q = 0.f;
    for (int i = 0; i < 64; ++i) { s += g_psum[i * C + c]; q += g_psq[i * C + c]; }
    const float invM = 1.0f / (float)MROWS;
    const float mu   = s * invM;
    const float var  = q * invM - mu * mu;
    const float a    = gam[c] * rsqrtf(var + EPSV);
    const float bb   = bet[c] - mu * a;
    if (which == 0) { g_A1[c] = a; g_B1[c] = bb; }
    else            { g_A2[c] = a; g_B2[c] = bb; }
}

// ---------------- attention: one block per (batch, head) ------------------------
__device__ __forceinline__ float hswish(float x)
{
    return x * __saturatef((x + 3.0f) * (1.0f / 6.0f));
}

__global__ void attn_kernel(const float* __restrict__ bias_table,
                            const int*   __restrict__ idxs)
{
    extern __shared__ float sm[];
    float* qs   = sm;                        // NTOK * 32
    float* ks   = qs  + NTOK * KDIM;         // NTOK * 33 (padded)
    float* vs   = ks  + NTOK * KS_STRIDE;    // NTOK * 128
    float* brow = vs  + NTOK * VDIM;         // NTOK
    float* S    = brow + NTOK;               // 8 * 200
    float* sA   = S   + 8 * S_STRIDE;        // 192
    float* sB   = sA  + HPC;                 // 192

    const int b   = blockIdx.x;
    const int h   = blockIdx.y;
    const int tid = threadIdx.x;             // 256 threads

    if (tid < HPC)  { sA[tid] = g_A1[h * HPC + tid]; sB[tid] = g_B1[h * HPC + tid]; }
    if (tid < NTOK) { brow[tid] = bias_table[h * NTOK + tid]; }
    __syncthreads();

    const size_t base = (size_t)(b * NTOK) * HIDC + h * HPC;
    for (int i = tid; i < NTOK * KDIM; i += 256) {
        const int n = i >> 5, d = i & 31;
        const size_t rb = base + (size_t)n * HIDC;
        qs[n * KDIM + d]      = g_Y[rb + d]        * sA[d]        + sB[d];
        ks[n * KS_STRIDE + d] = g_Y[rb + KDIM + d] * sA[KDIM + d] + sB[KDIM + d];
    }
    for (int i = tid; i < NTOK * VDIM; i += 256) {
        const int n = i >> 7, d = i & 127;
        vs[n * VDIM + d] = g_Y[base + (size_t)n * HIDC + 2 * KDIM + d]
                           * sA[2 * KDIM + d] + sB[2 * KDIM + d];
    }
    __syncthreads();

    const int w = tid >> 5, lane = tid & 31;

    for (int i0 = 0; i0 < NTOK; i0 += 8) {
        int nrow = NTOK - i0; if (nrow > 8) nrow = 8;

        for (int idx = tid; idx < nrow * NTOK; idx += 256) {
            const int i  = idx / NTOK;
            const int j  = idx - i * NTOK;
            const int qi = i0 + i;
            const float* qp = qs + qi * KDIM;
            const float* kp = ks + j * KS_STRIDE;
            float s = 0.f;
#pragma unroll
            for (int d = 0; d < KDIM; ++d) s = fmaf(qp[d], kp[d], s);
            S[i * S_STRIDE + j] = s * SCALEV + brow[idxs[qi * NTOK + j]];
        }
        __syncthreads();

        if (w < nrow) {
            float m = -1e30f;
            for (int j = lane; j < NTOK; j += 32) m = fmaxf(m, S[w * S_STRIDE + j]);
#pragma unroll
            for (int o = 16; o; o >>= 1) m = fmaxf(m, __shfl_xor_sync(0xffffffffu, m, o));
            float sum = 0.f;
            for (int j = lane; j < NTOK; j += 32) {
                float e = __expf(S[w * S_STRIDE + j] - m);
                S[w * S_STRIDE + j] = e;
                sum += e;
            }
#pragma unroll
            for (int o = 16; o; o >>= 1) sum += __shfl_xor_sync(0xffffffffu, sum, o);
            const float inv = 1.0f / sum;
            for (int j = lane; j < NTOK; j += 32) S[w * S_STRIDE + j] *= inv;
        }
        __syncthreads();

        if (w < nrow) {
            float4 acc = {0.f, 0.f, 0.f, 0.f};
            const float4* v4 = (const float4*)vs;
            const float*  Sp = S + w * S_STRIDE;
            for (int j = 0; j < NTOK; ++j) {
                const float p = Sp[j];
                const float4 v = v4[j * (VDIM / 4) + lane];
                acc.x = fmaf(p, v.x, acc.x);
                acc.y = fmaf(p, v.y, acc.y);
                acc.z = fmaf(p, v.z, acc.z);
                acc.w = fmaf(p, v.w, acc.w);
            }
            acc.x = hswish(acc.x); acc.y = hswish(acc.y);
            acc.z = hswish(acc.z); acc.w = hswish(acc.w);
            *(float4*)&g_O[(size_t)(b * NTOK + i0 + w) * DHC + h * VDIM + lane * 4] = acc;
        }
        __syncthreads();
    }
}

// ---------------- final BN apply (in place on d_out) ----------------------------
__global__ void norm2_kernel(float* __restrict__ Z)
{
    const size_t i = (size_t)blockIdx.x * 256 + threadIdx.x;   // float4 index
    float4 z = ((float4*)Z)[i];
    const int c4 = (int)(i & (DIMC / 4 - 1));
    const float4 a  = ((const float4*)g_A2)[c4];
    const float4 bb = ((const float4*)g_B2)[c4];
    z.x = fmaf(z.x, a.x, bb.x);
    z.y = fmaf(z.y, a.y, bb.y);
    z.z = fmaf(z.z, a.z, bb.z);
    z.w = fmaf(z.w, a.w, bb.w);
    ((float4*)Z)[i] = z;
}

// ---------------- launch ---------------------------------------------------------
static const size_t ATTN_SMEM_FLOATS =
    (size_t)NTOK * KDIM + (size_t)NTOK * KS_STRIDE + (size_t)NTOK * VDIM +
    NTOK + 8 * S_STRIDE + HPC + HPC;

extern "C" void kernel_launch(void* const* d_in, const int* in_sizes, int n_in,
                              void* d_out, int out_size)
{
    const float* x          = (const float*)d_in[0];
    const float* Wqkv       = (const float*)d_in[1];
    const float* g1         = (const float*)d_in[2];
    const float* b1         = (const float*)d_in[3];
    const float* bias_table = (const float*)d_in[4];
    const float* Wproj      = (const float*)d_in[5];
    const float* g2         = (const float*)d_in[6];
    const float* b2         = (const float*)d_in[7];
    const int*   idxs       = (const int*)d_in[8];
    float*       out        = (float*)d_out;

    float *Y, *O;
    cudaGetSymbolAddress((void**)&Y, g_Y);
    cudaGetSymbolAddress((void**)&O, g_O);

    const size_t attn_smem = ATTN_SMEM_FLOATS * sizeof(float);
    cudaFuncSetAttribute(attn_kernel, cudaFuncAttributeMaxDynamicSharedMemorySize,
                         (int)attn_smem);

    // 1) h = x @ Wqkv^T  (tf32 tensor cores)
    gemm_tf32<<<dim3(HIDC / 128, MROWS / 128), 256>>>(x, Wqkv, Y, MROWS, HIDC, DIMC);
    // 2) BN1 stats -> affine
    stats_partial<<<dim3(HIDC / 128, 64), 128>>>(Y, HIDC);
    stats_finalize<<<6, 256>>>(g1, b1, HIDC, 0);
    // 3) attention + hardswish
    attn_kernel<<<dim3(BATCHN, NHEAD), 256, attn_smem>>>(bias_table, idxs);
    // 4) Z = o @ Wproj^T  (tf32 tensor cores, into d_out)
    gemm_tf32<<<dim3(DIMC / 128, MROWS / 128), 256>>>(O, Wproj, out, MROWS, DIMC, DHC);
    // 5) BN2 stats -> affine
    stats_partial<<<dim3(DIMC / 128, 64), 128>>>(out, DIMC);
    stats_finalize<<<1, 256>>>(g2, b2, DIMC, 1);
    // 6) apply BN2 in place
    norm2_kernel<<<(MROWS * DIMC / 4) / 256, 256>>>(out);
}

// round 4
// speedup vs baseline: 1.9551x; 1.4785x over previous
#include <cuda_runtime.h>
#include <cstdint>

// ---------------- problem constants ----------------
#define BATCHN  256
#define NTOK    196
#define DIMC    256
#define NHEAD   8
#define KDIM    32
#define VDIM    128
#define HPC     192            // per-head channels in h (q32 + k32 + v128)
#define HIDC    1536
#define DHC     1024
#define EPSV    1e-5f
#define SCALEV  0.17677669529663687f   // 32^{-1/2}
#define MROWS   (BATCHN * NTOK)        // 50176

#define KSTR    36             // k row stride (floats): float4-aligned, conflict-free
#define SSTR    200            // score row stride (floats)
#define RTILE   64             // rows per score tile

// ---------------- scratch (device globals; no allocs allowed) ----------------
__device__ float g_Y[(size_t)MROWS * HIDC];     // h = x @ Wqkv^T   (308 MB)
__device__ float g_O[(size_t)MROWS * DHC];      // attention output (205 MB)
__device__ float g_psum[64 * HIDC];
__device__ float g_psq [64 * HIDC];
__device__ float g_A1[HIDC];
__device__ float g_B1[HIDC];
__device__ float g_A2[DIMC];
__device__ float g_B2[DIMC];

// ============================================================================
// TF32 tensor-core GEMM: C[M,N] = A[M,K] * B[N,K]^T  (row-major, K contiguous)
// ============================================================================

__device__ __forceinline__ unsigned f2tf(float f)
{
    unsigned u;
    asm("cvt.rna.tf32.f32 %0, %1;" : "=r"(u) : "f"(f));
    return u;
}

__device__ __forceinline__ int sw(int k, int x)
{
    return k * 136 + ((k >> 2) & 3) * 8 + x;
}

__device__ __forceinline__ void mma_tf32(float& d0, float& d1, float& d2, float& d3,
                                         unsigned a0, unsigned a1, unsigned a2, unsigned a3,
                                         unsigned b0, unsigned b1)
{
    asm volatile(
        "mma.sync.aligned.m16n8k8.row.col.f32.tf32.tf32.f32 "
        "{%0,%1,%2,%3}, {%4,%5,%6,%7}, {%8,%9}, {%0,%1,%2,%3};"
        : "+f"(d0), "+f"(d1), "+f"(d2), "+f"(d3)
        : "r"(a0), "r"(a1), "r"(a2), "r"(a3), "r"(b0), "r"(b1));
}

#define STG_WORDS 2208

__global__ void __launch_bounds__(256, 2)
gemm_tf32(const float* __restrict__ A, const float* __restrict__ B,
          float* __restrict__ C, int M, int N, int K)
{
    __shared__ unsigned smA[2][STG_WORDS];
    __shared__ unsigned smB[2][STG_WORDS];

    const int t    = threadIdx.x;
    const int lane = t & 31;
    const int w    = t >> 5;
    const int g    = lane >> 2;
    const int tig  = lane & 3;
    const int wM   = w >> 2;
    const int wN   = w & 3;
    const int m0   = blockIdx.y * 128;
    const int n0   = blockIdx.x * 128;

    const int r  = t >> 2;
    const int kc = (t & 3) * 4;

    const float* pA0 = A + (size_t)(m0 + r)      * K + kc;
    const float* pA1 = A + (size_t)(m0 + r + 64) * K + kc;
    const float* pB0 = B + (size_t)(n0 + r)      * K + kc;
    const float* pB1 = B + (size_t)(n0 + r + 64) * K + kc;

    float acc[4][4][4] = {};
    const int T = K / 16;

    {
        float4 va0 = *(const float4*)pA0;
        float4 va1 = *(const float4*)pA1;
        float4 vb0 = *(const float4*)pB0;
        float4 vb1 = *(const float4*)pB1;
        smA[0][sw(kc + 0, r)]      = f2tf(va0.x);
        smA[0][sw(kc + 1, r)]      = f2tf(va0.y);
        smA[0][sw(kc + 2, r)]      = f2tf(va0.z);
        smA[0][sw(kc + 3, r)]      = f2tf(va0.w);
        smA[0][sw(kc + 0, r + 64)] = f2tf(va1.x);
        smA[0][sw(kc + 1, r + 64)] = f2tf(va1.y);
        smA[0][sw(kc + 2, r + 64)] = f2tf(va1.z);
        smA[0][sw(kc + 3, r + 64)] = f2tf(va1.w);
        smB[0][sw(kc + 0, r)]      = f2tf(vb0.x);
        smB[0][sw(kc + 1, r)]      = f2tf(vb0.y);
        smB[0][sw(kc + 2, r)]      = f2tf(vb0.z);
        smB[0][sw(kc + 3, r)]      = f2tf(vb0.w);
        smB[0][sw(kc + 0, r + 64)] = f2tf(vb1.x);
        smB[0][sw(kc + 1, r + 64)] = f2tf(vb1.y);
        smB[0][sw(kc + 2, r + 64)] = f2tf(vb1.z);
        smB[0][sw(kc + 3, r + 64)] = f2tf(vb1.w);
    }
    __syncthreads();

    int buf = 0;
    for (int it = 0; it < T; ++it) {
        float4 va0, va1, vb0, vb1;
        const bool more = (it + 1) < T;
        if (more) {
            const int ko = (it + 1) * 16;
            va0 = *(const float4*)(pA0 + ko);
            va1 = *(const float4*)(pA1 + ko);
            vb0 = *(const float4*)(pB0 + ko);
            vb1 = *(const float4*)(pB1 + ko);
        }

        const unsigned* sA = smA[buf];
        const unsigned* sB = smB[buf];

#pragma unroll
        for (int kb = 0; kb < 16; kb += 8) {
            unsigned af[4][4];
            unsigned bfr[4][2];
#pragma unroll
            for (int ti = 0; ti < 4; ++ti) {
                const int m = wM * 64 + ti * 16 + g;
                af[ti][0] = sA[sw(kb + tig,     m)];
                af[ti][1] = sA[sw(kb + tig,     m + 8)];
                af[ti][2] = sA[sw(kb + tig + 4, m)];
                af[ti][3] = sA[sw(kb + tig + 4, m + 8)];
            }
#pragma unroll
            for (int tj = 0; tj < 4; ++tj) {
                const int n = wN * 32 + tj * 8 + g;
                bfr[tj][0] = sB[sw(kb + tig,     n)];
                bfr[tj][1] = sB[sw(kb + tig + 4, n)];
            }
#pragma unroll
            for (int ti = 0; ti < 4; ++ti)
#pragma unroll
                for (int tj = 0; tj < 4; ++tj)
                    mma_tf32(acc[ti][tj][0], acc[ti][tj][1], acc[ti][tj][2], acc[ti][tj][3],
                             af[ti][0], af[ti][1], af[ti][2], af[ti][3],
                             bfr[tj][0], bfr[tj][1]);
        }

        if (more) {
            const int nb = buf ^ 1;
            smA[nb][sw(kc + 0, r)]      = f2tf(va0.x);
            smA[nb][sw(kc + 1, r)]      = f2tf(va0.y);
            smA[nb][sw(kc + 2, r)]      = f2tf(va0.z);
            smA[nb][sw(kc + 3, r)]      = f2tf(va0.w);
            smA[nb][sw(kc + 0, r + 64)] = f2tf(va1.x);
            smA[nb][sw(kc + 1, r + 64)] = f2tf(va1.y);
            smA[nb][sw(kc + 2, r + 64)] = f2tf(va1.z);
            smA[nb][sw(kc + 3, r + 64)] = f2tf(va1.w);
            smB[nb][sw(kc + 0, r)]      = f2tf(vb0.x);
            smB[nb][sw(kc + 1, r)]      = f2tf(vb0.y);
            smB[nb][sw(kc + 2, r)]      = f2tf(vb0.z);
            smB[nb][sw(kc + 3, r)]      = f2tf(vb0.w);
            smB[nb][sw(kc + 0, r + 64)] = f2tf(vb1.x);
            smB[nb][sw(kc + 1, r + 64)] = f2tf(vb1.y);
            smB[nb][sw(kc + 2, r + 64)] = f2tf(vb1.z);
            smB[nb][sw(kc + 3, r + 64)] = f2tf(vb1.w);
        }
        __syncthreads();
        buf ^= 1;
    }

#pragma unroll
    for (int ti = 0; ti < 4; ++ti) {
#pragma unroll
        for (int tj = 0; tj < 4; ++tj) {
            const int row = m0 + wM * 64 + ti * 16 + g;
            const int col = n0 + wN * 32 + tj * 8 + 2 * tig;
            float2 lo = {acc[ti][tj][0], acc[ti][tj][1]};
            float2 hi = {acc[ti][tj][2], acc[ti][tj][3]};
            *(float2*)&C[(size_t)row * N + col]       = lo;
            *(float2*)&C[(size_t)(row + 8) * N + col] = hi;
        }
    }
}

// ---------------- BN stats: deterministic two-stage reduction -------------------
__global__ void stats_partial(const float* __restrict__ X, int C)
{
    const int c  = blockIdx.x * 128 + threadIdx.x;
    const int r0 = blockIdx.y * 784;
    float s = 0.f, q = 0.f;
    const float* p = X + (size_t)r0 * C + c;
    for (int r = 0; r < 784; ++r) {
        float v = p[(size_t)r * C];
        s += v;
        q += v * v;
    }
    g_psum[blockIdx.y * C + c] = s;
    g_psq [blockIdx.y * C + c] = q;
}

__global__ void stats_finalize(const float* __restrict__ gam, const float* __restrict__ bet,
                               int C, int which)
{
    const int c = blockIdx.x * blockDim.x + threadIdx.x;
    if (c >= C) return;
    float s = 0.f, q = 0.f;
    for (int i = 0; i < 64; ++i) { s += g_psum[i * C + c]; q += g_psq[i * C + c]; }
    const float invM = 1.0f / (float)MROWS;
    const float mu   = s * invM;
    const float var  = q * invM - mu * mu;
    const float a    = gam[c] * rsqrtf(var + EPSV);
    const float bb   = bet[c] - mu * a;
    if (which == 0) { g_A1[c] = a; g_B1[c] = bb; }
    else            { g_A2[c] = a; g_B2[c] = bb; }
}

// ============================================================================
// Attention: one block per (batch, head); 512 threads, 16 warps.
// smem: q[196x32], k[196x36 stride], v[196x128], S[64x200], bias row, affine.
// Scores: 2 rows/warp, q in registers, k via conflict-free LDS.128.
// PV:     4 rows/warp, v LDS.128 amortized x4, P via broadcast LDS.128.
// ============================================================================

__device__ __forceinline__ float hswish(float x)
{
    return x * __saturatef((x + 3.0f) * (1.0f / 6.0f));
}

#define ATTN_Q_OFF   0
#define ATTN_K_OFF   (NTOK * KDIM)                    // 6272
#define ATTN_V_OFF   (ATTN_K_OFF + NTOK * KSTR)       // 13328
#define ATTN_S_OFF   (ATTN_V_OFF + NTOK * VDIM)       // 38416
#define ATTN_BR_OFF  (ATTN_S_OFF + RTILE * SSTR)      // 51216
#define ATTN_A_OFF   (ATTN_BR_OFF + 200)              // 51416
#define ATTN_B_OFF   (ATTN_A_OFF + HPC)               // 51608
#define ATTN_FLOATS  (ATTN_B_OFF + HPC)               // 51800 -> 207200 B

__global__ void __launch_bounds__(512, 1)
attn_kernel(const float* __restrict__ bias_table,
            const int*   __restrict__ idxs)
{
    extern __shared__ float sm[];
    float* qs   = sm + ATTN_Q_OFF;
    float* ks   = sm + ATTN_K_OFF;
    float* vs   = sm + ATTN_V_OFF;
    float* S    = sm + ATTN_S_OFF;
    float* brow = sm + ATTN_BR_OFF;
    float* sA   = sm + ATTN_A_OFF;
    float* sB   = sm + ATTN_B_OFF;

    const int b    = blockIdx.x;
    const int h    = blockIdx.y;
    const int tid  = threadIdx.x;            // 512
    const int w    = tid >> 5;               // 0..15
    const int lane = tid & 31;

    if (tid < HPC)  { sA[tid] = g_A1[h * HPC + tid]; sB[tid] = g_B1[h * HPC + tid]; }
    if (tid < NTOK) { brow[tid] = bias_table[h * NTOK + tid]; }
    __syncthreads();

    // ---- load + normalize q,k,v (float4 granularity) ----
    const size_t base = (size_t)(b * NTOK) * HIDC + h * HPC;
    for (int i = tid; i < NTOK * (HPC / 4); i += 512) {
        const int n = i / (HPC / 4);
        const int c = (i - n * (HPC / 4)) * 4;
        float4 y = *(const float4*)&g_Y[base + (size_t)n * HIDC + c];
        const float4 a  = *(const float4*)&sA[c];
        const float4 bb = *(const float4*)&sB[c];
        y.x = fmaf(y.x, a.x, bb.x);
        y.y = fmaf(y.y, a.y, bb.y);
        y.z = fmaf(y.z, a.z, bb.z);
        y.w = fmaf(y.w, a.w, bb.w);
        float* dst;
        if (c < KDIM)          dst = &qs[n * KDIM + c];
        else if (c < 2 * KDIM) dst = &ks[n * KSTR + (c - KDIM)];
        else                   dst = &vs[n * VDIM + (c - 2 * KDIM)];
        *(float4*)dst = y;
    }
    __syncthreads();

    const float4* vs4 = (const float4*)vs;

    for (int tbase = 0; tbase < NTOK; tbase += RTILE) {
        int tcount = NTOK - tbase; if (tcount > RTILE) tcount = RTILE;

        // ---- scores: 2 rows per warp, up to 2 passes of 32 rows ----
#pragma unroll
        for (int pass = 0; pass < 2; ++pass) {
            const int rl0 = pass * 32 + 2 * w;
            if (rl0 < tcount) {
                const int rl1 = rl0 + 1;
                float4 qa[8], qb[8];
#pragma unroll
                for (int d4 = 0; d4 < 8; ++d4) {
                    qa[d4] = *(const float4*)&qs[(tbase + rl0) * KDIM + d4 * 4];
                    qb[d4] = *(const float4*)&qs[(tbase + rl1) * KDIM + d4 * 4];
                }
#pragma unroll
                for (int jt = 0; jt < 7; ++jt) {
                    const int j = lane + jt * 32;
                    if (j < NTOK) {
                        const float4* kp = (const float4*)&ks[j * KSTR];
                        float4 a0 = {0.f, 0.f, 0.f, 0.f};
                        float4 a1 = {0.f, 0.f, 0.f, 0.f};
#pragma unroll
                        for (int d4 = 0; d4 < 8; ++d4) {
                            const float4 kv = kp[d4];
                            a0.x = fmaf(qa[d4].x, kv.x, a0.x);
                            a0.y = fmaf(qa[d4].y, kv.y, a0.y);
                            a0.z = fmaf(qa[d4].z, kv.z, a0.z);
                            a0.w = fmaf(qa[d4].w, kv.w, a0.w);
                            a1.x = fmaf(qb[d4].x, kv.x, a1.x);
                            a1.y = fmaf(qb[d4].y, kv.y, a1.y);
                            a1.z = fmaf(qb[d4].z, kv.z, a1.z);
                            a1.w = fmaf(qb[d4].w, kv.w, a1.w);
                        }
                        const float s0 = (a0.x + a0.y) + (a0.z + a0.w);
                        const float s1 = (a1.x + a1.y) + (a1.z + a1.w);
                        S[rl0 * SSTR + j] = s0 * SCALEV + brow[idxs[(tbase + rl0) * NTOK + j]];
                        S[rl1 * SSTR + j] = s1 * SCALEV + brow[idxs[(tbase + rl1) * NTOK + j]];
                    }
                }
            }
        }
        __syncthreads();

        // ---- softmax: warp per row, strided over tile rows ----
        for (int rl = w; rl < tcount; rl += 16) {
            float* Sp = S + rl * SSTR;
            float m = -1e30f;
            for (int j = lane; j < NTOK; j += 32) m = fmaxf(m, Sp[j]);
#pragma unroll
            for (int o = 16; o; o >>= 1) m = fmaxf(m, __shfl_xor_sync(0xffffffffu, m, o));
            float sum = 0.f;
            for (int j = lane; j < NTOK; j += 32) {
                const float e = __expf(Sp[j] - m);
                Sp[j] = e;
                sum += e;
            }
#pragma unroll
            for (int o = 16; o; o >>= 1) sum += __shfl_xor_sync(0xffffffffu, sum, o);
            const float inv = 1.0f / sum;
            for (int j = lane; j < NTOK; j += 32) Sp[j] *= inv;
        }
        __syncthreads();

        // ---- PV: 4 rows per warp, lane owns 4 v-channels ----
        {
            const int q0 = 4 * w;
            if (q0 < tcount) {
                const float4* S4 = (const float4*)S;
                float4 acc0 = {0,0,0,0}, acc1 = {0,0,0,0}, acc2 = {0,0,0,0}, acc3 = {0,0,0,0};
#pragma unroll 7
                for (int jc = 0; jc < NTOK / 4; ++jc) {
                    const float4 v0 = vs4[(jc * 4 + 0) * (VDIM / 4) + lane];
                    const float4 v1 = vs4[(jc * 4 + 1) * (VDIM / 4) + lane];
                    const float4 v2 = vs4[(jc * 4 + 2) * (VDIM / 4) + lane];
                    const float4 v3 = vs4[(jc * 4 + 3) * (VDIM / 4) + lane];
                    const float4 p0 = S4[(q0 + 0) * (SSTR / 4) + jc];
                    const float4 p1 = S4[(q0 + 1) * (SSTR / 4) + jc];
                    const float4 p2 = S4[(q0 + 2) * (SSTR / 4) + jc];
                    const float4 p3 = S4[(q0 + 3) * (SSTR / 4) + jc];

                    acc0.x = fmaf(p0.x, v0.x, acc0.x); acc0.y = fmaf(p0.x, v0.y, acc0.y);
                    acc0.z = fmaf(p0.x, v0.z, acc0.z); acc0.w = fmaf(p0.x, v0.w, acc0.w);
                    acc0.x = fmaf(p0.y, v1.x, acc0.x); acc0.y = fmaf(p0.y, v1.y, acc0.y);
                    acc0.z = fmaf(p0.y, v1.z, acc0.z); acc0.w = fmaf(p0.y, v1.w, acc0.w);
                    acc0.x = fmaf(p0.z, v2.x, acc0.x); acc0.y = fmaf(p0.z, v2.y, acc0.y);
                    acc0.z = fmaf(p0.z, v2.z, acc0.z); acc0.w = fmaf(p0.z, v2.w, acc0.w);
                    acc0.x = fmaf(p0.w, v3.x, acc0.x); acc0.y = fmaf(p0.w, v3.y, acc0.y);
                    acc0.z = fmaf(p0.w, v3.z, acc0.z); acc0.w = fmaf(p0.w, v3.w, acc0.w);

                    acc1.x = fmaf(p1.x, v0.x, acc1.x); acc1.y = fmaf(p1.x, v0.y, acc1.y);
                    acc1.z = fmaf(p1.x, v0.z, acc1.z); acc1.w = fmaf(p1.x, v0.w, acc1.w);
                    acc1.x = fmaf(p1.y, v1.x, acc1.x); acc1.y = fmaf(p1.y, v1.y, acc1.y);
                    acc1.z = fmaf(p1.y, v1.z, acc1.z); acc1.w = fmaf(p1.y, v1.w, acc1.w);
                    acc1.x = fmaf(p1.z, v2.x, acc1.x); acc1.y = fmaf(p1.z, v2.y, acc1.y);
                    acc1.z = fmaf(p1.z, v2.z, acc1.z); acc1.w = fmaf(p1.z, v2.w, acc1.w);
                    acc1.x = fmaf(p1.w, v3.x, acc1.x); acc1.y = fmaf(p1.w, v3.y, acc1.y);
                    acc1.z = fmaf(p1.w, v3.z, acc1.z); acc1.w = fmaf(p1.w, v3.w, acc1.w);

                    acc2.x = fmaf(p2.x, v0.x, acc2.x); acc2.y = fmaf(p2.x, v0.y, acc2.y);
                    acc2.z = fmaf(p2.x, v0.z, acc2.z); acc2.w = fmaf(p2.x, v0.w, acc2.w);
                    acc2.x = fmaf(p2.y, v1.x, acc2.x); acc2.y = fmaf(p2.y, v1.y, acc2.y);
                    acc2.z = fmaf(p2.y, v1.z, acc2.z); acc2.w = fmaf(p2.y, v1.w, acc2.w);
                    acc2.x = fmaf(p2.z, v2.x, acc2.x); acc2.y = fmaf(p2.z, v2.y, acc2.y);
                    acc2.z = fmaf(p2.z, v2.z, acc2.z); acc2.w = fmaf(p2.z, v2.w, acc2.w);
                    acc2.x = fmaf(p2.w, v3.x, acc2.x); acc2.y = fmaf(p2.w, v3.y, acc2.y);
                    acc2.z = fmaf(p2.w, v3.z, acc2.z); acc2.w = fmaf(p2.w, v3.w, acc2.w);

                    acc3.x = fmaf(p3.x, v0.x, acc3.x); acc3.y = fmaf(p3.x, v0.y, acc3.y);
                    acc3.z = fmaf(p3.x, v0.z, acc3.z); acc3.w = fmaf(p3.x, v0.w, acc3.w);
                    acc3.x = fmaf(p3.y, v1.x, acc3.x); acc3.y = fmaf(p3.y, v1.y, acc3.y);
                    acc3.z = fmaf(p3.y, v1.z, acc3.z); acc3.w = fmaf(p3.y, v1.w, acc3.w);
                    acc3.x = fmaf(p3.z, v2.x, acc3.x); acc3.y = fmaf(p3.z, v2.y, acc3.y);
                    acc3.z = fmaf(p3.z, v2.z, acc3.z); acc3.w = fmaf(p3.z, v2.w, acc3.w);
                    acc3.x = fmaf(p3.w, v3.x, acc3.x); acc3.y = fmaf(p3.w, v3.y, acc3.y);
                    acc3.z = fmaf(p3.w, v3.z, acc3.z); acc3.w = fmaf(p3.w, v3.w, acc3.w);
                }

                float4 o[4] = {acc0, acc1, acc2, acc3};
#pragma unroll
                for (int r2 = 0; r2 < 4; ++r2) {
                    if (q0 + r2 < tcount) {
                        float4 z = o[r2];
                        z.x = hswish(z.x); z.y = hswish(z.y);
                        z.z = hswish(z.z); z.w = hswish(z.w);
                        *(float4*)&g_O[(size_t)(b * NTOK + tbase + q0 + r2) * DHC
                                       + h * VDIM + lane * 4] = z;
                    }
                }
            }
        }
        __syncthreads();
    }
}

// ---------------- final BN apply (in place on d_out) ----------------------------
__global__ void norm2_kernel(float* __restrict__ Z)
{
    const size_t i = (size_t)blockIdx.x * 256 + threadIdx.x;
    float4 z = ((float4*)Z)[i];
    const int c4 = (int)(i & (DIMC / 4 - 1));
    const float4 a  = ((const float4*)g_A2)[c4];
    const float4 bb = ((const float4*)g_B2)[c4];
    z.x = fmaf(z.x, a.x, bb.x);
    z.y = fmaf(z.y, a.y, bb.y);
    z.z = fmaf(z.z, a.z, bb.z);
    z.w = fmaf(z.w, a.w, bb.w);
    ((float4*)Z)[i] = z;
}

// ---------------- launch ---------------------------------------------------------
extern "C" void kernel_launch(void* const* d_in, const int* in_sizes, int n_in,
                              void* d_out, int out_size)
{
    const float* x          = (const float*)d_in[0];
    const float* Wqkv       = (const float*)d_in[1];
    const float* g1         = (const float*)d_in[2];
    const float* b1         = (const float*)d_in[3];
    const float* bias_table = (const float*)d_in[4];
    const float* Wproj      = (const float*)d_in[5];
    const float* g2         = (const float*)d_in[6];
    const float* b2         = (const float*)d_in[7];
    const int*   idxs       = (const int*)d_in[8];
    float*       out        = (float*)d_out;

    float *Y, *O;
    cudaGetSymbolAddress((void**)&Y, g_Y);
    cudaGetSymbolAddress((void**)&O, g_O);

    const size_t attn_smem = (size_t)ATTN_FLOATS * sizeof(float);
    cudaFuncSetAttribute(attn_kernel, cudaFuncAttributeMaxDynamicSharedMemorySize,
                         (int)attn_smem);

    // 1) h = x @ Wqkv^T  (tf32 tensor cores)
    gemm_tf32<<<dim3(HIDC / 128, MROWS / 128), 256>>>(x, Wqkv, Y, MROWS, HIDC, DIMC);
    // 2) BN1 stats -> affine
    stats_partial<<<dim3(HIDC / 128, 64), 128>>>(Y, HIDC);
    stats_finalize<<<6, 256>>>(g1, b1, HIDC, 0);
    // 3) attention + hardswish
    attn_kernel<<<dim3(BATCHN, NHEAD), 512, attn_smem>>>(bias_table, idxs);
    // 4) Z = o @ Wproj^T  (tf32 tensor cores, into d_out)
    gemm_tf32<<<dim3(DIMC / 128, MROWS / 128), 256>>>(O, Wproj, out, MROWS, DIMC, DHC);
    // 5) BN2 stats -> affine
    stats_partial<<<dim3(DIMC / 128, 64), 128>>>(out, DIMC);
    stats_finalize<<<1, 256>>>(g2, b2, DIMC, 1);
    // 6) apply BN2 in place
    norm2_kernel<<<(MROWS * DIMC / 4) / 256, 256>>>(out);
}

// round 8
// speedup vs baseline: 3.3936x; 1.7358x over previous
#include <cuda_runtime.h>
#include <cuda_fp16.h>
#include <cstdint>

// ---------------- problem constants ----------------
#define BATCHN  256
#define NTOK    196
#define DIMC    256
#define NHEAD   8
#define KDIM    32
#define VDIM    128
#define HPC     192            // per-head channels in h (q32 + k32 + v128)
#define HIDC    1536
#define DHC     1024
#define EPSV    1e-5f
#define SCALEV  0.17677669529663687f   // 32^{-1/2}
#define MROWS   (BATCHN * NTOK)        // 50176

#define KSTR    36             // k row stride (floats): float4-aligned, conflict-free
#define SSTR    200            // score row stride (floats)
#define RTILE   64             // rows per score tile

// ---------------- scratch (device globals; no allocs allowed) ----------------
__device__ float g_Y[(size_t)MROWS * HIDC];     // h = x @ Wqkv^T   (308 MB)
__device__ float g_O[(size_t)MROWS * DHC];      // attention output (205 MB)
__device__ float g_psum[64 * HIDC];
__device__ float g_psq [64 * HIDC];
__device__ float g_A1[HIDC];
__device__ float g_B1[HIDC];
__device__ float g_A2[DIMC];
__device__ float g_B2[DIMC];

// ============================================================================
// FP16 tensor-core GEMM: C[M,N] = A[M,K] * B[N,K]^T  (row-major, K contiguous)
// Tile 128x128x16, 256 threads, warp grid 2(M) x 4(N), warp tile 64x32,
// mma.sync.m16n8k16.f16 (fp32 accum). SMEM in half2 words:
//   addr(k2, x) = k2*136 + ((k2>>2)&1)*8 + x
// conflict-free for both staging STS and all fragment LDS (verified by bank
// arithmetic: stores hit banks {0,16,8,24}+g', loads hit 8*tig+g(+8)).
// ============================================================================

__device__ __forceinline__ int sw2(int k2, int x)
{
    return k2 * 136 + ((k2 >> 2) & 1) * 8 + x;
}

__device__ __forceinline__ void mma_f16(float& d0, float& d1, float& d2, float& d3,
                                        unsigned a0, unsigned a1, unsigned a2, unsigned a3,
                                        unsigned b0, unsigned b1)
{
    asm volatile(
        "mma.sync.aligned.m16n8k16.row.col.f32.f16.f16.f32 "
        "{%0,%1,%2,%3}, {%4,%5,%6,%7}, {%8,%9}, {%0,%1,%2,%3};"
        : "+f"(d0), "+f"(d1), "+f"(d2), "+f"(d3)
        : "r"(a0), "r"(a1), "r"(a2), "r"(a3), "r"(b0), "r"(b1));
}

__device__ __forceinline__ unsigned pack2(float lo, float hi)
{
    __half2 h = __floats2half2_rn(lo, hi);
    return *reinterpret_cast<unsigned*>(&h);
}

#define STG2_WORDS 1088   // 7*136 + 8 + 128 = 1088 half2 words per buffer

__global__ void __launch_bounds__(256, 2)
gemm_f16(const float* __restrict__ A, const float* __restrict__ B,
         float* __restrict__ C, int M, int N, int K)
{
    __shared__ unsigned smA[2][STG2_WORDS];
    __shared__ unsigned smB[2][STG2_WORDS];

    const int t    = threadIdx.x;
    const int lane = t & 31;
    const int w    = t >> 5;
    const int g    = lane >> 2;      // 0..7
    const int tig  = lane & 3;       // 0..3
    const int wM   = w >> 2;         // 0..1
    const int wN   = w & 3;          // 0..3
    const int m0   = blockIdx.y * 128;
    const int n0   = blockIdx.x * 128;

    // staging: thread loads rows (r, r+64), k-cols kc..kc+3 (float4)
    const int r  = t >> 2;           // 0..63
    const int kc = (t & 3) * 4;      // 0,4,8,12
    const int k2c = kc >> 1;         // 0,2,4,6

    const float* pA0 = A + (size_t)(m0 + r)      * K + kc;
    const float* pA1 = A + (size_t)(m0 + r + 64) * K + kc;
    const float* pB0 = B + (size_t)(n0 + r)      * K + kc;
    const float* pB1 = B + (size_t)(n0 + r + 64) * K + kc;

    float acc[4][4][4] = {};
    const int T = K / 16;

    // ---- prologue: stage tile 0 ----
    {
        float4 va0 = *(const float4*)pA0;
        float4 va1 = *(const float4*)pA1;
        float4 vb0 = *(const float4*)pB0;
        float4 vb1 = *(const float4*)pB1;
        smA[0][sw2(k2c,     r)]      = pack2(va0.x, va0.y);
        smA[0][sw2(k2c + 1, r)]      = pack2(va0.z, va0.w);
        smA[0][sw2(k2c,     r + 64)] = pack2(va1.x, va1.y);
        smA[0][sw2(k2c + 1, r + 64)] = pack2(va1.z, va1.w);
        smB[0][sw2(k2c,     r)]      = pack2(vb0.x, vb0.y);
        smB[0][sw2(k2c + 1, r)]      = pack2(vb0.z, vb0.w);
        smB[0][sw2(k2c,     r + 64)] = pack2(vb1.x, vb1.y);
        smB[0][sw2(k2c + 1, r + 64)] = pack2(vb1.z, vb1.w);
    }
    __syncthreads();

    int buf = 0;
    for (int it = 0; it < T; ++it) {
        float4 va0, va1, vb0, vb1;
        const bool more = (it + 1) < T;
        if (more) {
            const int ko = (it + 1) * 16;
            va0 = *(const float4*)(pA0 + ko);
            va1 = *(const float4*)(pA1 + ko);
            vb0 = *(const float4*)(pB0 + ko);
            vb1 = *(const float4*)(pB1 + ko);
        }

        const unsigned* sA = smA[buf];
        const unsigned* sB = smB[buf];

        // one m16n8k16 pass covers all K=16 of this tile
        {
            unsigned af[4][4];
            unsigned bfr[4][2];
#pragma unroll
            for (int ti = 0; ti < 4; ++ti) {
                const int m = wM * 64 + ti * 16 + g;
                af[ti][0] = sA[sw2(tig,     m)];      // (row g,   k 2tig..2tig+1)
                af[ti][1] = sA[sw2(tig,     m + 8)];  // (row g+8, k 2tig..2tig+1)
                af[ti][2] = sA[sw2(tig + 4, m)];      // (row g,   k 2tig+8..+9)
                af[ti][3] = sA[sw2(tig + 4, m + 8)];  // (row g+8, k 2tig+8..+9)
            }
#pragma unroll
            for (int tj = 0; tj < 4; ++tj) {
                const int n = wN * 32 + tj * 8 + g;
                bfr[tj][0] = sB[sw2(tig,     n)];
                bfr[tj][1] = sB[sw2(tig + 4, n)];
            }
#pragma unroll
            for (int ti = 0; ti < 4; ++ti)
#pragma unroll
                for (int tj = 0; tj < 4; ++tj)
                    mma_f16(acc[ti][tj][0], acc[ti][tj][1], acc[ti][tj][2], acc[ti][tj][3],
                            af[ti][0], af[ti][1], af[ti][2], af[ti][3],
                            bfr[tj][0], bfr[tj][1]);
        }

        if (more) {
            const int nb = buf ^ 1;
            smA[nb][sw2(k2c,     r)]      = pack2(va0.x, va0.y);
            smA[nb][sw2(k2c + 1, r)]      = pack2(va0.z, va0.w);
            smA[nb][sw2(k2c,     r + 64)] = pack2(va1.x, va1.y);
            smA[nb][sw2(k2c + 1, r + 64)] = pack2(va1.z, va1.w);
            smB[nb][sw2(k2c,     r)]      = pack2(vb0.x, vb0.y);
            smB[nb][sw2(k2c + 1, r)]      = pack2(vb0.z, vb0.w);
            smB[nb][sw2(k2c,     r + 64)] = pack2(vb1.x, vb1.y);
            smB[nb][sw2(k2c + 1, r + 64)] = pack2(vb1.z, vb1.w);
        }
        __syncthreads();
        buf ^= 1;
    }

    // ---- epilogue (same lane mapping as m16n8k8) ----
#pragma unroll
    for (int ti = 0; ti < 4; ++ti) {
#pragma unroll
        for (int tj = 0; tj < 4; ++tj) {
            const int row = m0 + wM * 64 + ti * 16 + g;
            const int col = n0 + wN * 32 + tj * 8 + 2 * tig;
            float2 lo = {acc[ti][tj][0], acc[ti][tj][1]};
            float2 hi = {acc[ti][tj][2], acc[ti][tj][3]};
            *(float2*)&C[(size_t)row * N + col]       = lo;
            *(float2*)&C[(size_t)(row + 8) * N + col] = hi;
        }
    }
}

// ---------------- BN stats: deterministic two-stage reduction -------------------
__global__ void stats_partial(const float* __restrict__ X, int C)
{
    const int c  = blockIdx.x * 128 + threadIdx.x;
    const int r0 = blockIdx.y * 784;
    float s = 0.f, q = 0.f;
    const float* p = X + (size_t)r0 * C + c;
    for (int r = 0; r < 784; ++r) {
        float v = p[(size_t)r * C];
        s += v;
        q += v * v;
    }
    g_psum[blockIdx.y * C + c] = s;
    g_psq [blockIdx.y * C + c] = q;
}

__global__ void stats_finalize(const float* __restrict__ gam, const float* __restrict__ bet,
                               int C, int which)
{
    const int c = blockIdx.x * blockDim.x + threadIdx.x;
    if (c >= C) return;
    float s = 0.f, q = 0.f;
    for (int i = 0; i < 64; ++i) { s += g_psum[i * C + c]; q += g_psq[i * C + c]; }
    const float invM = 1.0f / (float)MROWS;
    const float mu   = s * invM;
    const float var  = q * invM - mu * mu;
    const float a    = gam[c] * rsqrtf(var + EPSV);
    const float bb   = bet[c] - mu * a;
    if (which == 0) { g_A1[c] = a; g_B1[c] = bb; }
    else            { g_A2[c] = a; g_B2[c] = bb; }
}

// ============================================================================
// Attention: one block per (batch, head); 512 threads, 16 warps.
// ============================================================================

__device__ __forceinline__ float hswish(float x)
{
    return x * __saturatef((x + 3.0f) * (1.0f / 6.0f));
}

#define ATTN_Q_OFF   0
#define ATTN_K_OFF   (NTOK * KDIM)                    // 6272
#define ATTN_V_OFF   (ATTN_K_OFF + NTOK * KSTR)       // 13328
#define ATTN_S_OFF   (ATTN_V_OFF + NTOK * VDIM)       // 38416
#define ATTN_BR_OFF  (ATTN_S_OFF + RTILE * SSTR)      // 51216
#define ATTN_A_OFF   (ATTN_BR_OFF + 200)              // 51416
#define ATTN_B_OFF   (ATTN_A_OFF + HPC)               // 51608
#define ATTN_FLOATS  (ATTN_B_OFF + HPC)               // 51800 -> 207200 B

__global__ void __launch_bounds__(512, 1)
attn_kernel(const float* __restrict__ bias_table,
            const int*   __restrict__ idxs)
{
    extern __shared__ float sm[];
    float* qs   = sm + ATTN_Q_OFF;
    float* ks   = sm + ATTN_K_OFF;
    float* vs   = sm + ATTN_V_OFF;
    float* S    = sm + ATTN_S_OFF;
    float* brow = sm + ATTN_BR_OFF;
    float* sA   = sm + ATTN_A_OFF;
    float* sB   = sm + ATTN_B_OFF;

    const int b    = blockIdx.x;
    const int h    = blockIdx.y;
    const int tid  = threadIdx.x;            // 512
    const int w    = tid >> 5;               // 0..15
    const int lane = tid & 31;

    if (tid < HPC)  { sA[tid] = g_A1[h * HPC + tid]; sB[tid] = g_B1[h * HPC + tid]; }
    if (tid < NTOK) { brow[tid] = bias_table[h * NTOK + tid]; }
    __syncthreads();

    const size_t base = (size_t)(b * NTOK) * HIDC + h * HPC;
    for (int i = tid; i < NTOK * (HPC / 4); i += 512) {
        const int n = i / (HPC / 4);
        const int c = (i - n * (HPC / 4)) * 4;
        float4 y = *(const float4*)&g_Y[base + (size_t)n * HIDC + c];
        const float4 a  = *(const float4*)&sA[c];
        const float4 bb = *(const float4*)&sB[c];
        y.x = fmaf(y.x, a.x, bb.x);
        y.y = fmaf(y.y, a.y, bb.y);
        y.z = fmaf(y.z, a.z, bb.z);
        y.w = fmaf(y.w, a.w, bb.w);
        float* dst;
        if (c < KDIM)          dst = &qs[n * KDIM + c];
        else if (c < 2 * KDIM) dst = &ks[n * KSTR + (c - KDIM)];
        else                   dst = &vs[n * VDIM + (c - 2 * KDIM)];
        *(float4*)dst = y;
    }
    __syncthreads();

    const float4* vs4 = (const float4*)vs;

    for (int tbase = 0; tbase < NTOK; tbase += RTILE) {
        int tcount = NTOK - tbase; if (tcount > RTILE) tcount = RTILE;

        // ---- scores: 2 rows per warp ----
#pragma unroll
        for (int pass = 0; pass < 2; ++pass) {
            const int rl0 = pass * 32 + 2 * w;
            if (rl0 < tcount) {
                const int rl1 = rl0 + 1;
                float4 qa[8], qb[8];
#pragma unroll
                for (int d4 = 0; d4 < 8; ++d4) {
                    qa[d4] = *(const float4*)&qs[(tbase + rl0) * KDIM + d4 * 4];
                    qb[d4] = *(const float4*)&qs[(tbase + rl1) * KDIM + d4 * 4];
                }
#pragma unroll
                for (int jt = 0; jt < 7; ++jt) {
                    const int j = lane + jt * 32;
                    if (j < NTOK) {
                        const float4* kp = (const float4*)&ks[j * KSTR];
                        float4 a0 = {0.f, 0.f, 0.f, 0.f};
                        float4 a1 = {0.f, 0.f, 0.f, 0.f};
#pragma unroll
                        for (int d4 = 0; d4 < 8; ++d4) {
                            const float4 kv = kp[d4];
                            a0.x = fmaf(qa[d4].x, kv.x, a0.x);
                            a0.y = fmaf(qa[d4].y, kv.y, a0.y);
                            a0.z = fmaf(qa[d4].z, kv.z, a0.z);
                            a0.w = fmaf(qa[d4].w, kv.w, a0.w);
                            a1.x = fmaf(qb[d4].x, kv.x, a1.x);
                            a1.y = fmaf(qb[d4].y, kv.y, a1.y);
                            a1.z = fmaf(qb[d4].z, kv.z, a1.z);
                            a1.w = fmaf(qb[d4].w, kv.w, a1.w);
                        }
                        const float s0 = (a0.x + a0.y) + (a0.z + a0.w);
                        const float s1 = (a1.x + a1.y) + (a1.z + a1.w);
                        S[rl0 * SSTR + j] = s0 * SCALEV + brow[idxs[(tbase + rl0) * NTOK + j]];
                        S[rl1 * SSTR + j] = s1 * SCALEV + brow[idxs[(tbase + rl1) * NTOK + j]];
                    }
                }
            }
        }
        __syncthreads();

        // ---- softmax: warp per row ----
        for (int rl = w; rl < tcount; rl += 16) {
            float* Sp = S + rl * SSTR;
            float m = -1e30f;
            for (int j = lane; j < NTOK; j += 32) m = fmaxf(m, Sp[j]);
#pragma unroll
            for (int o = 16; o; o >>= 1) m = fmaxf(m, __shfl_xor_sync(0xffffffffu, m, o));
            float sum = 0.f;
            for (int j = lane; j < NTOK; j += 32) {
                const float e = __expf(Sp[j] - m);
                Sp[j] = e;
                sum += e;
            }
#pragma unroll
            for (int o = 16; o; o >>= 1) sum += __shfl_xor_sync(0xffffffffu, sum, o);
            const float inv = 1.0f / sum;
            for (int j = lane; j < NTOK; j += 32) Sp[j] *= inv;
        }
        __syncthreads();

        // ---- PV: 4 rows per warp, lane owns 4 v-channels ----
        {
            const int q0 = 4 * w;
            if (q0 < tcount) {
                const float4* S4 = (const float4*)S;
                float4 acc0 = {0,0,0,0}, acc1 = {0,0,0,0}, acc2 = {0,0,0,0}, acc3 = {0,0,0,0};
#pragma unroll 7
                for (int jc = 0; jc < NTOK / 4; ++jc) {
                    const float4 v0 = vs4[(jc * 4 + 0) * (VDIM / 4) + lane];
                    const float4 v1 = vs4[(jc * 4 + 1) * (VDIM / 4) + lane];
                    const float4 v2 = vs4[(jc * 4 + 2) * (VDIM / 4) + lane];
                    const float4 v3 = vs4[(jc * 4 + 3) * (VDIM / 4) + lane];
                    const float4 p0 = S4[(q0 + 0) * (SSTR / 4) + jc];
                    const float4 p1 = S4[(q0 + 1) * (SSTR / 4) + jc];
                    const float4 p2 = S4[(q0 + 2) * (SSTR / 4) + jc];
                    const float4 p3 = S4[(q0 + 3) * (SSTR / 4) + jc];

                    acc0.x = fmaf(p0.x, v0.x, acc0.x); acc0.y = fmaf(p0.x, v0.y, acc0.y);
                    acc0.z = fmaf(p0.x, v0.z, acc0.z); acc0.w = fmaf(p0.x, v0.w, acc0.w);
                    acc0.x = fmaf(p0.y, v1.x, acc0.x); acc0.y = fmaf(p0.y, v1.y, acc0.y);
                    acc0.z = fmaf(p0.y, v1.z, acc0.z); acc0.w = fmaf(p0.y, v1.w, acc0.w);
                    acc0.x = fmaf(p0.z, v2.x, acc0.x); acc0.y = fmaf(p0.z, v2.y, acc0.y);
                    acc0.z = fmaf(p0.z, v2.z, acc0.z); acc0.w = fmaf(p0.z, v2.w, acc0.w);
                    acc0.x = fmaf(p0.w, v3.x, acc0.x); acc0.y = fmaf(p0.w, v3.y, acc0.y);
                    acc0.z = fmaf(p0.w, v3.z, acc0.z); acc0.w = fmaf(p0.w, v3.w, acc0.w);

                    acc1.x = fmaf(p1.x, v0.x, acc1.x); acc1.y = fmaf(p1.x, v0.y, acc1.y);
                    acc1.z = fmaf(p1.x, v0.z, acc1.z); acc1.w = fmaf(p1.x, v0.w, acc1.w);
                    acc1.x = fmaf(p1.y, v1.x, acc1.x); acc1.y = fmaf(p1.y, v1.y, acc1.y);
                    acc1.z = fmaf(p1.y, v1.z, acc1.z); acc1.w = fmaf(p1.y, v1.w, acc1.w);
                    acc1.x = fmaf(p1.z, v2.x, acc1.x); acc1.y = fmaf(p1.z, v2.y, acc1.y);
                    acc1.z = fmaf(p1.z, v2.z, acc1.z); acc1.w = fmaf(p1.z, v2.w, acc1.w);
                    acc1.x = fmaf(p1.w, v3.x, acc1.x); acc1.y = fmaf(p1.w, v3.y, acc1.y);
                    acc1.z = fmaf(p1.w, v3.z, acc1.z); acc1.w = fmaf(p1.w, v3.w, acc1.w);

                    acc2.x = fmaf(p2.x, v0.x, acc2.x); acc2.y = fmaf(p2.x, v0.y, acc2.y);
                    acc2.z = fmaf(p2.x, v0.z, acc2.z); acc2.w = fmaf(p2.x, v0.w, acc2.w);
                    acc2.x = fmaf(p2.y, v1.x, acc2.x); acc2.y = fmaf(p2.y, v1.y, acc2.y);
                    acc2.z = fmaf(p2.y, v1.z, acc2.z); acc2.w = fmaf(p2.y, v1.w, acc2.w);
                    acc2.x = fmaf(p2.z, v2.x, acc2.x); acc2.y = fmaf(p2.z, v2.y, acc2.y);
                    acc2.z = fmaf(p2.z, v2.z, acc2.z); acc2.w = fmaf(p2.z, v2.w, acc2.w);
                    acc2.x = fmaf(p2.w, v3.x, acc2.x); acc2.y = fmaf(p2.w, v3.y, acc2.y);
                    acc2.z = fmaf(p2.w, v3.z, acc2.z); acc2.w = fmaf(p2.w, v3.w, acc2.w);

                    acc3.x = fmaf(p3.x, v0.x, acc3.x); acc3.y = fmaf(p3.x, v0.y, acc3.y);
                    acc3.z = fmaf(p3.x, v0.z, acc3.z); acc3.w = fmaf(p3.x, v0.w, acc3.w);
                    acc3.x = fmaf(p3.y, v1.x, acc3.x); acc3.y = fmaf(p3.y, v1.y, acc3.y);
                    acc3.z = fmaf(p3.y, v1.z, acc3.z); acc3.w = fmaf(p3.y, v1.w, acc3.w);
                    acc3.x = fmaf(p3.z, v2.x, acc3.x); acc3.y = fmaf(p3.z, v2.y, acc3.y);
                    acc3.z = fmaf(p3.z, v2.z, acc3.z); acc3.w = fmaf(p3.z, v2.w, acc3.w);
                    acc3.x = fmaf(p3.w, v3.x, acc3.x); acc3.y = fmaf(p3.w, v3.y, acc3.y);
                    acc3.z = fmaf(p3.w, v3.z, acc3.z); acc3.w = fmaf(p3.w, v3.w, acc3.w);
                }

                float4 o[4] = {acc0, acc1, acc2, acc3};
#pragma unroll
                for (int r2 = 0; r2 < 4; ++r2) {
                    if (q0 + r2 < tcount) {
                        float4 z = o[r2];
                        z.x = hswish(z.x); z.y = hswish(z.y);
                        z.z = hswish(z.z); z.w = hswish(z.w);
                        *(float4*)&g_O[(size_t)(b * NTOK + tbase + q0 + r2) * DHC
                                       + h * VDIM + lane * 4] = z;
                    }
                }
            }
        }
        __syncthreads();
    }
}

// ---------------- final BN apply (in place on d_out) ----------------------------
__global__ void norm2_kernel(float* __restrict__ Z)
{
    const size_t i = (size_t)blockIdx.x * 256 + threadIdx.x;
    float4 z = ((float4*)Z)[i];
    const int c4 = (int)(i & (DIMC / 4 - 1));
    const float4 a  = ((const float4*)g_A2)[c4];
    const float4 bb = ((const float4*)g_B2)[c4];
    z.x = fmaf(z.x, a.x, bb.x);
    z.y = fmaf(z.y, a.y, bb.y);
    z.z = fmaf(z.z, a.z, bb.z);
    z.w = fmaf(z.w, a.w, bb.w);
    ((float4*)Z)[i] = z;
}

// ---------------- launch ---------------------------------------------------------
extern "C" void kernel_launch(void* const* d_in, const int* in_sizes, int n_in,
                              void* d_out, int out_size)
{
    const float* x          = (const float*)d_in[0];
    const float* Wqkv       = (const float*)d_in[1];
    const float* g1         = (const float*)d_in[2];
    const float* b1         = (const float*)d_in[3];
    const float* bias_table = (const float*)d_in[4];
    const float* Wproj      = (const float*)d_in[5];
    const float* g2         = (const float*)d_in[6];
    const float* b2         = (const float*)d_in[7];
    const int*   idxs       = (const int*)d_in[8];
    float*       out        = (float*)d_out;

    float *Y, *O;
    cudaGetSymbolAddress((void**)&Y, g_Y);
    cudaGetSymbolAddress((void**)&O, g_O);

    const size_t attn_smem = (size_t)ATTN_FLOATS * sizeof(float);
    cudaFuncSetAttribute(attn_kernel, cudaFuncAttributeMaxDynamicSharedMemorySize,
                         (int)attn_smem);

    // 1) h = x @ Wqkv^T  (fp16 tensor cores, fp32 accum)
    gemm_f16<<<dim3(HIDC / 128, MROWS / 128), 256>>>(x, Wqkv, Y, MROWS, HIDC, DIMC);
    // 2) BN1 stats -> affine
    stats_partial<<<dim3(HIDC / 128, 64), 128>>>(Y, HIDC);
    stats_finalize<<<6, 256>>>(g1, b1, HIDC, 0);
    // 3) attention + hardswish
    attn_kernel<<<dim3(BATCHN, NHEAD), 512, attn_smem>>>(bias_table, idxs);
    // 4) Z = o @ Wproj^T  (fp16 tensor cores, into d_out)
    gemm_f16<<<dim3(DIMC / 128, MROWS / 128), 256>>>(O, Wproj, out, MROWS, DIMC, DHC);
    // 5) BN2 stats -> affine
    stats_partial<<<dim3(DIMC / 128, 64), 128>>>(out, DIMC);
    stats_finalize<<<1, 256>>>(g2, b2, DIMC, 1);
    // 6) apply BN2 in place
    norm2_kernel<<<(MROWS * DIMC / 4) / 256, 256>>>(out);
}

// round 11
// speedup vs baseline: 4.5250x; 1.3334x over previous
#include <cuda_runtime.h>
#include <cuda_fp16.h>
#include <cstdint>

// ---------------- problem constants ----------------
#define BATCHN  256
#define NTOK    196
#define DIMC    256
#define NHEAD   8
#define KDIM    32
#define VDIM    128
#define HPC     192            // per-head channels in h (q32 + k32 + v128)
#define HIDC    1536
#define DHC     1024
#define EPSV    1e-5f
#define SCALEV  0.17677669529663687f   // 32^{-1/2}
#define MROWS   (BATCHN * NTOK)        // 50176

// ---------------- scratch (device globals; no allocs allowed) ----------------
__device__ float g_Y[(size_t)MROWS * HIDC];     // h = x @ Wqkv^T   (308 MB)
__device__ float g_O[(size_t)MROWS * DHC];      // attention output (205 MB)
__device__ float g_psum[64 * HIDC];
__device__ float g_psq [64 * HIDC];
__device__ float g_A1[HIDC];
__device__ float g_B1[HIDC];
__device__ float g_A2[DIMC];
__device__ float g_B2[DIMC];

// ---------------- shared helpers ----------------
__device__ __forceinline__ void mma_f16(float& d0, float& d1, float& d2, float& d3,
                                        unsigned a0, unsigned a1, unsigned a2, unsigned a3,
                                        unsigned b0, unsigned b1)
{
    asm volatile(
        "mma.sync.aligned.m16n8k16.row.col.f32.f16.f16.f32 "
        "{%0,%1,%2,%3}, {%4,%5,%6,%7}, {%8,%9}, {%0,%1,%2,%3};"
        : "+f"(d0), "+f"(d1), "+f"(d2), "+f"(d3)
        : "r"(a0), "r"(a1), "r"(a2), "r"(a3), "r"(b0), "r"(b1));
}

__device__ __forceinline__ unsigned pack2(float lo, float hi)
{
    __half2 h = __floats2half2_rn(lo, hi);
    return *reinterpret_cast<unsigned*>(&h);
}

// ============================================================================
// FP16 tensor-core GEMM: C[M,N] = A[M,K] * B[N,K]^T  (row-major, K contiguous)
// ============================================================================

__device__ __forceinline__ int sw2(int k2, int x)
{
    return k2 * 136 + ((k2 >> 2) & 1) * 8 + x;
}

#define STG2_WORDS 1088

__global__ void __launch_bounds__(256, 2)
gemm_f16(const float* __restrict__ A, const float* __restrict__ B,
         float* __restrict__ C, int M, int N, int K)
{
    __shared__ unsigned smA[2][STG2_WORDS];
    __shared__ unsigned smB[2][STG2_WORDS];

    const int t    = threadIdx.x;
    const int lane = t & 31;
    const int w    = t >> 5;
    const int g    = lane >> 2;
    const int tig  = lane & 3;
    const int wM   = w >> 2;
    const int wN   = w & 3;
    const int m0   = blockIdx.y * 128;
    const int n0   = blockIdx.x * 128;

    const int r  = t >> 2;
    const int kc = (t & 3) * 4;
    const int k2c = kc >> 1;

    const float* pA0 = A + (size_t)(m0 + r)      * K + kc;
    const float* pA1 = A + (size_t)(m0 + r + 64) * K + kc;
    const float* pB0 = B + (size_t)(n0 + r)      * K + kc;
    const float* pB1 = B + (size_t)(n0 + r + 64) * K + kc;

    float acc[4][4][4] = {};
    const int T = K / 16;

    {
        float4 va0 = *(const float4*)pA0;
        float4 va1 = *(const float4*)pA1;
        float4 vb0 = *(const float4*)pB0;
        float4 vb1 = *(const float4*)pB1;
        smA[0][sw2(k2c,     r)]      = pack2(va0.x, va0.y);
        smA[0][sw2(k2c + 1, r)]      = pack2(va0.z, va0.w);
        smA[0][sw2(k2c,     r + 64)] = pack2(va1.x, va1.y);
        smA[0][sw2(k2c + 1, r + 64)] = pack2(va1.z, va1.w);
        smB[0][sw2(k2c,     r)]      = pack2(vb0.x, vb0.y);
        smB[0][sw2(k2c + 1, r)]      = pack2(vb0.z, vb0.w);
        smB[0][sw2(k2c,     r + 64)] = pack2(vb1.x, vb1.y);
        smB[0][sw2(k2c + 1, r + 64)] = pack2(vb1.z, vb1.w);
    }
    __syncthreads();

    int buf = 0;
    for (int it = 0; it < T; ++it) {
        float4 va0, va1, vb0, vb1;
        const bool more = (it + 1) < T;
        if (more) {
            const int ko = (it + 1) * 16;
            va0 = *(const float4*)(pA0 + ko);
            va1 = *(const float4*)(pA1 + ko);
            vb0 = *(const float4*)(pB0 + ko);
            vb1 = *(const float4*)(pB1 + ko);
        }

        const unsigned* sA = smA[buf];
        const unsigned* sB = smB[buf];

        {
            unsigned af[4][4];
            unsigned bfr[4][2];
#pragma unroll
            for (int ti = 0; ti < 4; ++ti) {
                const int m = wM * 64 + ti * 16 + g;
                af[ti][0] = sA[sw2(tig,     m)];
                af[ti][1] = sA[sw2(tig,     m + 8)];
                af[ti][2] = sA[sw2(tig + 4, m)];
                af[ti][3] = sA[sw2(tig + 4, m + 8)];
            }
#pragma unroll
            for (int tj = 0; tj < 4; ++tj) {
                const int n = wN * 32 + tj * 8 + g;
                bfr[tj][0] = sB[sw2(tig,     n)];
                bfr[tj][1] = sB[sw2(tig + 4, n)];
            }
#pragma unroll
            for (int ti = 0; ti < 4; ++ti)
#pragma unroll
                for (int tj = 0; tj < 4; ++tj)
                    mma_f16(acc[ti][tj][0], acc[ti][tj][1], acc[ti][tj][2], acc[ti][tj][3],
                            af[ti][0], af[ti][1], af[ti][2], af[ti][3],
                            bfr[tj][0], bfr[tj][1]);
        }

        if (more) {
            const int nb = buf ^ 1;
            smA[nb][sw2(k2c,     r)]      = pack2(va0.x, va0.y);
            smA[nb][sw2(k2c + 1, r)]      = pack2(va0.z, va0.w);
            smA[nb][sw2(k2c,     r + 64)] = pack2(va1.x, va1.y);
            smA[nb][sw2(k2c + 1, r + 64)] = pack2(va1.z, va1.w);
            smB[nb][sw2(k2c,     r)]      = pack2(vb0.x, vb0.y);
            smB[nb][sw2(k2c + 1, r)]      = pack2(vb0.z, vb0.w);
            smB[nb][sw2(k2c,     r + 64)] = pack2(vb1.x, vb1.y);
            smB[nb][sw2(k2c + 1, r + 64)] = pack2(vb1.z, vb1.w);
        }
        __syncthreads();
        buf ^= 1;
    }

#pragma unroll
    for (int ti = 0; ti < 4; ++ti) {
#pragma unroll
        for (int tj = 0; tj < 4; ++tj) {
            const int row = m0 + wM * 64 + ti * 16 + g;
            const int col = n0 + wN * 32 + tj * 8 + 2 * tig;
            float2 lo = {acc[ti][tj][0], acc[ti][tj][1]};
            float2 hi = {acc[ti][tj][2], acc[ti][tj][3]};
            *(float2*)&C[(size_t)row * N + col]       = lo;
            *(float2*)&C[(size_t)(row + 8) * N + col] = hi;
        }
    }
}

// ---------------- BN stats: deterministic two-stage reduction -------------------
__global__ void stats_partial(const float* __restrict__ X, int C)
{
    const int c  = blockIdx.x * 128 + threadIdx.x;
    const int r0 = blockIdx.y * 784;
    float s = 0.f, q = 0.f;
    const float* p = X + (size_t)r0 * C + c;
    for (int r = 0; r < 784; ++r) {
        float v = p[(size_t)r * C];
        s += v;
        q += v * v;
    }
    g_psum[blockIdx.y * C + c] = s;
    g_psq [blockIdx.y * C + c] = q;
}

__global__ void stats_finalize(const float* __restrict__ gam, const float* __restrict__ bet,
                               int C, int which)
{
    const int c = blockIdx.x * blockDim.x + threadIdx.x;
    if (c >= C) return;
    float s = 0.f, q = 0.f;
    for (int i = 0; i < 64; ++i) { s += g_psum[i * C + c]; q += g_psq[i * C + c]; }
    const float invM = 1.0f / (float)MROWS;
    const float mu   = s * invM;
    const float var  = q * invM - mu * mu;
    const float a    = gam[c] * rsqrtf(var + EPSV);
    const float bb   = bet[c] - mu * a;
    if (which == 0) { g_A1[c] = a; g_B1[c] = bb; }
    else            { g_A2[c] = a; g_B2[c] = bb; }
}

// ============================================================================
// Tensor-core attention: one block per (batch, head); 512 threads, 16 warps.
// smem (u32 words):
//   Qh  [208][20]  fp16 q rows (stride 40 halves)          @ 0      (4160)
//   Kh  [208][20]  fp16 k rows                             @ 4160   (4160)
//   VhT [128][108] fp16 V transposed [channel][token]      @ 8320   (13824)
//   S   [64][212]  fp32 scores                             @ 22144  (13568)
//   Ph  [64][108]  fp16 probabilities (stride 216 halves)  @ 35712  (6912)
//   brow[196] sA[192] sB[192]                              @ 42624..
// total 43204 u32 = 172816 B
// ============================================================================

#define AOFF_Q   0
#define AOFF_K   4160
#define AOFF_V   8320
#define AOFF_S   22144
#define AOFF_P   35712
#define AOFF_BR  42624
#define AOFF_A   42820
#define AOFF_B   43012
#define AOFF_TOT 43204

__device__ __forceinline__ float hswish(float x)
{
    return x * __saturatef((x + 3.0f) * (1.0f / 6.0f));
}

__global__ void __launch_bounds__(512, 1)
attn_kernel(const float* __restrict__ bias_table,
            const int*   __restrict__ idxs)
{
    extern __shared__ float sm[];
    unsigned* usm  = reinterpret_cast<unsigned*>(sm);
    unsigned* uQ   = usm + AOFF_Q;
    unsigned* uK   = usm + AOFF_K;
    unsigned* uV   = usm + AOFF_V;
    float*    S    = sm  + AOFF_S;
    unsigned* uP   = usm + AOFF_P;
    float*    brow = sm  + AOFF_BR;
    float*    sA   = sm  + AOFF_A;
    float*    sB   = sm  + AOFF_B;

    const int b    = blockIdx.x;
    const int h    = blockIdx.y;
    const int tid  = threadIdx.x;            // 512
    const int w    = tid >> 5;               // 0..15
    const int lane = tid & 31;
    const int g    = lane >> 2;              // 0..7
    const int tig  = lane & 3;               // 0..3

    if (tid < HPC)  { sA[tid] = g_A1[h * HPC + tid]; sB[tid] = g_B1[h * HPC + tid]; }
    if (tid < NTOK) { brow[tid] = bias_table[h * NTOK + tid]; }

    // zero pads: Q/K rows 196..207, V token columns 196..215
    for (int i = tid; i < 12 * 20; i += 512) {
        const int rr = 196 + i / 20, cc = i % 20;
        uQ[rr * 20 + cc] = 0;
        uK[rr * 20 + cc] = 0;
    }
    for (int i = tid; i < 128 * 10; i += 512)
        uV[(i / 10) * 108 + 98 + (i % 10)] = 0;
    __syncthreads();

    // ---- load + BN-normalize + fp16 convert ----
    const size_t base = (size_t)(b * NTOK) * HIDC + h * HPC;
    for (int i = tid; i < NTOK * (HPC / 4); i += 512) {
        const int n  = i / (HPC / 4);
        const int c4 = (i - n * (HPC / 4)) * 4;
        float4 y = *(const float4*)&g_Y[base + (size_t)n * HIDC + c4];
        const float4 a  = *(const float4*)&sA[c4];
        const float4 bb = *(const float4*)&sB[c4];
        y.x = fmaf(y.x, a.x, bb.x);
        y.y = fmaf(y.y, a.y, bb.y);
        y.z = fmaf(y.z, a.z, bb.z);
        y.w = fmaf(y.w, a.w, bb.w);
        if (c4 < KDIM) {
            uQ[n * 20 + c4 / 2]     = pack2(y.x, y.y);
            uQ[n * 20 + c4 / 2 + 1] = pack2(y.z, y.w);
        } else if (c4 < 2 * KDIM) {
            const int cc = c4 - KDIM;
            uK[n * 20 + cc / 2]     = pack2(y.x, y.y);
            uK[n * 20 + cc / 2 + 1] = pack2(y.z, y.w);
        } else {
            const int ch = c4 - 2 * KDIM;
            __half* hv = reinterpret_cast<__half*>(uV);
            hv[(ch + 0) * 216 + n] = __float2half(y.x);
            hv[(ch + 1) * 216 + n] = __float2half(y.y);
            hv[(ch + 2) * 216 + n] = __float2half(y.z);
            hv[(ch + 3) * 216 + n] = __float2half(y.w);
        }
    }
    __syncthreads();

    const int rb = w >> 2;           // 0..3: 16-row block within 64-row tile
    const int ws = w & 3;            // 0..3: work split within phase
    const int r0 = rb * 16;

    for (int tbase = 0; tbase < NTOK; tbase += 64) {
        const int tcount = (NTOK - tbase < 64) ? (NTOK - tbase) : 64;

        // ---- QK^T + scale + bias -> S (fp32) ----
        if (r0 < tcount) {
            const int rowg = tbase + r0 + g;
            unsigned aq0 = uQ[rowg * 20 + tig];
            unsigned aq1 = uQ[(rowg + 8) * 20 + tig];
            unsigned aq2 = uQ[rowg * 20 + tig + 4];
            unsigned aq3 = uQ[(rowg + 8) * 20 + tig + 4];
            unsigned aq4 = uQ[rowg * 20 + 8 + tig];
            unsigned aq5 = uQ[(rowg + 8) * 20 + 8 + tig];
            unsigned aq6 = uQ[rowg * 20 + 8 + tig + 4];
            unsigned aq7 = uQ[(rowg + 8) * 20 + 8 + tig + 4];

            const int rA = r0 + g, rB = r0 + g + 8;
            for (int j = ws; j < 26; j += 4) {
                const int tok = 8 * j + g;
                const unsigned b00 = uK[tok * 20 + tig];
                const unsigned b01 = uK[tok * 20 + tig + 4];
                const unsigned b10 = uK[tok * 20 + 8 + tig];
                const unsigned b11 = uK[tok * 20 + 8 + tig + 4];
                float c0 = 0.f, c1 = 0.f, c2 = 0.f, c3 = 0.f;
                mma_f16(c0, c1, c2, c3, aq0, aq1, aq2, aq3, b00, b01);
                mma_f16(c0, c1, c2, c3, aq4, aq5, aq6, aq7, b10, b11);
                const int col0 = 8 * j + 2 * tig;
                const int col1 = col0 + 1;
                if (rA < tcount) {
                    S[rA * 212 + col0] = (col0 < NTOK)
                        ? fmaf(c0, SCALEV, brow[idxs[(tbase + rA) * NTOK + col0]]) : -1e30f;
                    S[rA * 212 + col1] = (col1 < NTOK)
                        ? fmaf(c1, SCALEV, brow[idxs[(tbase + rA) * NTOK + col1]]) : -1e30f;
                }
                if (rB < tcount) {
                    S[rB * 212 + col0] = (col0 < NTOK)
                        ? fmaf(c2, SCALEV, brow[idxs[(tbase + rB) * NTOK + col0]]) : -1e30f;
                    S[rB * 212 + col1] = (col1 < NTOK)
                        ? fmaf(c3, SCALEV, brow[idxs[(tbase + rB) * NTOK + col1]]) : -1e30f;
                }
            }
        }
        __syncthreads();

        // ---- softmax rows (fp32) -> Ph (fp16, normalized, zero-padded) ----
        for (int rl = w; rl < tcount; rl += 16) {
            float* Sp = S + rl * 212;
            float m = -1e30f;
            for (int j = lane; j < NTOK; j += 32) m = fmaxf(m, Sp[j]);
#pragma unroll
            for (int o = 16; o; o >>= 1) m = fmaxf(m, __shfl_xor_sync(0xffffffffu, m, o));
            float sum = 0.f;
            for (int j = lane; j < NTOK; j += 32) {
                const float e = __expf(Sp[j] - m);
                Sp[j] = e;
                sum += e;
            }
#pragma unroll
            for (int o = 16; o; o >>= 1) sum += __shfl_xor_sync(0xffffffffu, sum, o);
            const float inv = 1.0f / sum;
            for (int jj = lane; jj < 108; jj += 32) {
                const int ca = 2 * jj, cb = 2 * jj + 1;
                const float v0 = (ca < NTOK) ? Sp[ca] * inv : 0.f;
                const float v1 = (cb < NTOK) ? Sp[cb] * inv : 0.f;
                uP[rl * 108 + jj] = pack2(v0, v1);
            }
        }
        __syncthreads();

        // ---- PV (fp16 mma) + hswish -> g_O ----
        if (r0 < tcount) {
            float acc[4][4] = {};
#pragma unroll
            for (int ks = 0; ks < 13; ++ks) {
                const int ko = 8 * ks;
                const unsigned pa0 = uP[(r0 + g) * 108 + ko + tig];
                const unsigned pa1 = uP[(r0 + g + 8) * 108 + ko + tig];
                const unsigned pa2 = uP[(r0 + g) * 108 + ko + tig + 4];
                const unsigned pa3 = uP[(r0 + g + 8) * 108 + ko + tig + 4];
#pragma unroll
                for (int nj = 0; nj < 4; ++nj) {
                    const int ch = ws * 32 + 8 * nj + g;
                    const unsigned vb0 = uV[ch * 108 + ko + tig];
                    const unsigned vb1 = uV[ch * 108 + ko + tig + 4];
                    mma_f16(acc[nj][0], acc[nj][1], acc[nj][2], acc[nj][3],
                            pa0, pa1, pa2, pa3, vb0, vb1);
                }
            }
            const int rA = r0 + g, rB = r0 + g + 8;
#pragma unroll
            for (int nj = 0; nj < 4; ++nj) {
                const int col = h * VDIM + ws * 32 + 8 * nj + 2 * tig;
                if (rA < tcount) {
                    float2 v = {hswish(acc[nj][0]), hswish(acc[nj][1])};
                    *(float2*)&g_O[(size_t)(b * NTOK + tbase + rA) * DHC + col] = v;
                }
                if (rB < tcount) {
                    float2 v = {hswish(acc[nj][2]), hswish(acc[nj][3])};
                    *(float2*)&g_O[(size_t)(b * NTOK + tbase + rB) * DHC + col] = v;
                }
            }
        }
        __syncthreads();
    }
}

// ---------------- final BN apply (in place on d_out) ----------------------------
__global__ void norm2_kernel(float* __restrict__ Z)
{
    const size_t i = (size_t)blockIdx.x * 256 + threadIdx.x;
    float4 z = ((float4*)Z)[i];
    const int c4 = (int)(i & (DIMC / 4 - 1));
    const float4 a  = ((const float4*)g_A2)[c4];
    const float4 bb = ((const float4*)g_B2)[c4];
    z.x = fmaf(z.x, a.x, bb.x);
    z.y = fmaf(z.y, a.y, bb.y);
    z.z = fmaf(z.z, a.z, bb.z);
    z.w = fmaf(z.w, a.w, bb.w);
    ((float4*)Z)[i] = z;
}

// ---------------- launch ---------------------------------------------------------
extern "C" void kernel_launch(void* const* d_in, const int* in_sizes, int n_in,
                              void* d_out, int out_size)
{
    const float* x          = (const float*)d_in[0];
    const float* Wqkv       = (const float*)d_in[1];
    const float* g1         = (const float*)d_in[2];
    const float* b1         = (const float*)d_in[3];
    const float* bias_table = (const float*)d_in[4];
    const float* Wproj      = (const float*)d_in[5];
    const float* g2         = (const float*)d_in[6];
    const float* b2         = (const float*)d_in[7];
    const int*   idxs       = (const int*)d_in[8];
    float*       out        = (float*)d_out;

    float *Y, *O;
    cudaGetSymbolAddress((void**)&Y, g_Y);
    cudaGetSymbolAddress((void**)&O, g_O);

    const size_t attn_smem = (size_t)AOFF_TOT * sizeof(float);
    cudaFuncSetAttribute(attn_kernel, cudaFuncAttributeMaxDynamicSharedMemorySize,
                         (int)attn_smem);

    // 1) h = x @ Wqkv^T  (fp16 tensor cores, fp32 accum)
    gemm_f16<<<dim3(HIDC / 128, MROWS / 128), 256>>>(x, Wqkv, Y, MROWS, HIDC, DIMC);
    // 2) BN1 stats -> affine
    stats_partial<<<dim3(HIDC / 128, 64), 128>>>(Y, HIDC);
    stats_finalize<<<6, 256>>>(g1, b1, HIDC, 0);
    // 3) attention + hardswish (fp16 tensor cores)
    attn_kernel<<<dim3(BATCHN, NHEAD), 512, attn_smem>>>(bias_table, idxs);
    // 4) Z = o @ Wproj^T  (fp16 tensor cores, into d_out)
    gemm_f16<<<dim3(DIMC / 128, MROWS / 128), 256>>>(O, Wproj, out, MROWS, DIMC, DHC);
    // 5) BN2 stats -> affine
    stats_partial<<<dim3(DIMC / 128, 64), 128>>>(out, DIMC);
    stats_finalize<<<1, 256>>>(g2, b2, DIMC, 1);
    // 6) apply BN2 in place
    norm2_kernel<<<(MROWS * DIMC / 4) / 256, 256>>>(out);
}

// round 12
// speedup vs baseline: 4.8238x; 1.0660x over previous
#include <cuda_runtime.h>
#include <cuda_fp16.h>
#include <cstdint>

// ---------------- problem constants ----------------
#define BATCHN  256
#define NTOK    196
#define DIMC    256
#define NHEAD   8
#define KDIM    32
#define VDIM    128
#define HPC     192            // per-head channels in h (q32 + k32 + v128)
#define HIDC    1536
#define DHC     1024
#define EPSV    1e-5f
#define SCALEV  0.17677669529663687f   // 32^{-1/2}
#define MROWS   (BATCHN * NTOK)        // 50176

// ---------------- scratch (device globals; no allocs allowed) ----------------
__device__ float g_Y[(size_t)MROWS * HIDC];     // h = x @ Wqkv^T   (308 MB)
__device__ float g_O[(size_t)MROWS * DHC];      // attention output (205 MB)
__device__ float g_bias[NHEAD * NTOK * NTOK];   // expanded bias (1.23 MB, L2-resident)
__device__ float g_psum[64 * HIDC];
__device__ float g_psq [64 * HIDC];
__device__ float g_A1[HIDC];
__device__ float g_B1[HIDC];
__device__ float g_A2[DIMC];
__device__ float g_B2[DIMC];

// ---------------- shared helpers ----------------
__device__ __forceinline__ void mma_f16(float& d0, float& d1, float& d2, float& d3,
                                        unsigned a0, unsigned a1, unsigned a2, unsigned a3,
                                        unsigned b0, unsigned b1)
{
    asm volatile(
        "mma.sync.aligned.m16n8k16.row.col.f32.f16.f16.f32 "
        "{%0,%1,%2,%3}, {%4,%5,%6,%7}, {%8,%9}, {%0,%1,%2,%3};"
        : "+f"(d0), "+f"(d1), "+f"(d2), "+f"(d3)
        : "r"(a0), "r"(a1), "r"(a2), "r"(a3), "r"(b0), "r"(b1));
}

__device__ __forceinline__ unsigned pack2(float lo, float hi)
{
    __half2 h = __floats2half2_rn(lo, hi);
    return *reinterpret_cast<unsigned*>(&h);
}

// ============================================================================
// FP16 tensor-core GEMM: C[M,N] = A[M,K] * B[N,K]^T  (row-major, K contiguous)
// ============================================================================

__device__ __forceinline__ int sw2(int k2, int x)
{
    return k2 * 136 + ((k2 >> 2) & 1) * 8 + x;
}

#define STG2_WORDS 1088

__global__ void __launch_bounds__(256, 2)
gemm_f16(const float* __restrict__ A, const float* __restrict__ B,
         float* __restrict__ C, int M, int N, int K)
{
    __shared__ unsigned smA[2][STG2_WORDS];
    __shared__ unsigned smB[2][STG2_WORDS];

    const int t    = threadIdx.x;
    const int lane = t & 31;
    const int w    = t >> 5;
    const int g    = lane >> 2;
    const int tig  = lane & 3;
    const int wM   = w >> 2;
    const int wN   = w & 3;
    const int m0   = blockIdx.y * 128;
    const int n0   = blockIdx.x * 128;

    const int r  = t >> 2;
    const int kc = (t & 3) * 4;
    const int k2c = kc >> 1;

    const float* pA0 = A + (size_t)(m0 + r)      * K + kc;
    const float* pA1 = A + (size_t)(m0 + r + 64) * K + kc;
    const float* pB0 = B + (size_t)(n0 + r)      * K + kc;
    const float* pB1 = B + (size_t)(n0 + r + 64) * K + kc;

    float acc[4][4][4] = {};
    const int T = K / 16;

    {
        float4 va0 = *(const float4*)pA0;
        float4 va1 = *(const float4*)pA1;
        float4 vb0 = *(const float4*)pB0;
        float4 vb1 = *(const float4*)pB1;
        smA[0][sw2(k2c,     r)]      = pack2(va0.x, va0.y);
        smA[0][sw2(k2c + 1, r)]      = pack2(va0.z, va0.w);
        smA[0][sw2(k2c,     r + 64)] = pack2(va1.x, va1.y);
        smA[0][sw2(k2c + 1, r + 64)] = pack2(va1.z, va1.w);
        smB[0][sw2(k2c,     r)]      = pack2(vb0.x, vb0.y);
        smB[0][sw2(k2c + 1, r)]      = pack2(vb0.z, vb0.w);
        smB[0][sw2(k2c,     r + 64)] = pack2(vb1.x, vb1.y);
        smB[0][sw2(k2c + 1, r + 64)] = pack2(vb1.z, vb1.w);
    }
    __syncthreads();

    int buf = 0;
    for (int it = 0; it < T; ++it) {
        float4 va0, va1, vb0, vb1;
        const bool more = (it + 1) < T;
        if (more) {
            const int ko = (it + 1) * 16;
            va0 = *(const float4*)(pA0 + ko);
            va1 = *(const float4*)(pA1 + ko);
            vb0 = *(const float4*)(pB0 + ko);
            vb1 = *(const float4*)(pB1 + ko);
        }

        const unsigned* sA = smA[buf];
        const unsigned* sB = smB[buf];

        {
            unsigned af[4][4];
            unsigned bfr[4][2];
#pragma unroll
            for (int ti = 0; ti < 4; ++ti) {
                const int m = wM * 64 + ti * 16 + g;
                af[ti][0] = sA[sw2(tig,     m)];
                af[ti][1] = sA[sw2(tig,     m + 8)];
                af[ti][2] = sA[sw2(tig + 4, m)];
                af[ti][3] = sA[sw2(tig + 4, m + 8)];
            }
#pragma unroll
            for (int tj = 0; tj < 4; ++tj) {
                const int n = wN * 32 + tj * 8 + g;
                bfr[tj][0] = sB[sw2(tig,     n)];
                bfr[tj][1] = sB[sw2(tig + 4, n)];
            }
#pragma unroll
            for (int ti = 0; ti < 4; ++ti)
#pragma unroll
                for (int tj = 0; tj < 4; ++tj)
                    mma_f16(acc[ti][tj][0], acc[ti][tj][1], acc[ti][tj][2], acc[ti][tj][3],
                            af[ti][0], af[ti][1], af[ti][2], af[ti][3],
                            bfr[tj][0], bfr[tj][1]);
        }

        if (more) {
            const int nb = buf ^ 1;
            smA[nb][sw2(k2c,     r)]      = pack2(va0.x, va0.y);
            smA[nb][sw2(k2c + 1, r)]      = pack2(va0.z, va0.w);
            smA[nb][sw2(k2c,     r + 64)] = pack2(va1.x, va1.y);
            smA[nb][sw2(k2c + 1, r + 64)] = pack2(va1.z, va1.w);
            smB[nb][sw2(k2c,     r)]      = pack2(vb0.x, vb0.y);
            smB[nb][sw2(k2c + 1, r)]      = pack2(vb0.z, vb0.w);
            smB[nb][sw2(k2c,     r + 64)] = pack2(vb1.x, vb1.y);
            smB[nb][sw2(k2c + 1, r + 64)] = pack2(vb1.z, vb1.w);
        }
        __syncthreads();
        buf ^= 1;
    }

#pragma unroll
    for (int ti = 0; ti < 4; ++ti) {
#pragma unroll
        for (int tj = 0; tj < 4; ++tj) {
            const int row = m0 + wM * 64 + ti * 16 + g;
            const int col = n0 + wN * 32 + tj * 8 + 2 * tig;
            float2 lo = {acc[ti][tj][0], acc[ti][tj][1]};
            float2 hi = {acc[ti][tj][2], acc[ti][tj][3]};
            *(float2*)&C[(size_t)row * N + col]       = lo;
            *(float2*)&C[(size_t)(row + 8) * N + col] = hi;
        }
    }
}

// ---------------- bias expansion: bias_full[h,i,j] = bias_table[h, idxs[i,j]] ----
__global__ void bias_expand(const float* __restrict__ bias_table,
                            const int*   __restrict__ idxs)
{
    const int i = blockIdx.x * 512 + threadIdx.x;
    if (i >= NHEAD * NTOK * NTOK) return;
    const int h  = i / (NTOK * NTOK);
    const int rc = i - h * NTOK * NTOK;
    g_bias[i] = bias_table[h * NTOK + idxs[rc]];
}

// ---------------- BN stats: deterministic two-stage reduction -------------------
__global__ void stats_partial(const float* __restrict__ X, int C)
{
    const int c  = blockIdx.x * 128 + threadIdx.x;
    const int r0 = blockIdx.y * 784;
    float s = 0.f, q = 0.f;
    const float* p = X + (size_t)r0 * C + c;
    for (int r = 0; r < 784; ++r) {
        float v = p[(size_t)r * C];
        s += v;
        q += v * v;
    }
    g_psum[blockIdx.y * C + c] = s;
    g_psq [blockIdx.y * C + c] = q;
}

__global__ void stats_finalize(const float* __restrict__ gam, const float* __restrict__ bet,
                               int C, int which)
{
    const int c = blockIdx.x * blockDim.x + threadIdx.x;
    if (c >= C) return;
    float s = 0.f, q = 0.f;
    for (int i = 0; i < 64; ++i) { s += g_psum[i * C + c]; q += g_psq[i * C + c]; }
    const float invM = 1.0f / (float)MROWS;
    const float mu   = s * invM;
    const float var  = q * invM - mu * mu;
    const float a    = gam[c] * rsqrtf(var + EPSV);
    const float bb   = bet[c] - mu * a;
    if (which == 0) { g_A1[c] = a; g_B1[c] = bb; }
    else            { g_A2[c] = a; g_B2[c] = bb; }
}

// ============================================================================
// Tensor-core attention: one block per (batch, head); 512 threads, 16 warps.
// smem (u32 words):
//   Qh  [208][20]  fp16 q rows (stride 40 halves)          @ 0      (4160)
//   Kh  [208][20]  fp16 k rows                             @ 4160   (4160)
//   VhT [128][108] fp16 V transposed [channel][token]      @ 8320   (13824)
//   S   [64][212]  fp32 scores                             @ 22144  (13568)
//   Ph  [64][108]  fp16 probabilities (stride 216 halves)  @ 35712  (6912)
//   sA[192] sB[192]                                        @ 42624..
// total 43008 u32 = 172032 B
// ============================================================================

#define AOFF_Q   0
#define AOFF_K   4160
#define AOFF_V   8320
#define AOFF_S   22144
#define AOFF_P   35712
#define AOFF_A   42624
#define AOFF_B   42816
#define AOFF_TOT 43008

__device__ __forceinline__ float hswish(float x)
{
    return x * __saturatef((x + 3.0f) * (1.0f / 6.0f));
}

__global__ void __launch_bounds__(512, 1)
attn_kernel(const float* __restrict__ dummy)
{
    extern __shared__ float sm[];
    unsigned* usm  = reinterpret_cast<unsigned*>(sm);
    unsigned* uQ   = usm + AOFF_Q;
    unsigned* uK   = usm + AOFF_K;
    unsigned* uV   = usm + AOFF_V;
    float*    S    = sm  + AOFF_S;
    unsigned* uP   = usm + AOFF_P;
    float*    sA   = sm  + AOFF_A;
    float*    sB   = sm  + AOFF_B;

    const int b    = blockIdx.x;
    const int h    = blockIdx.y;
    const int tid  = threadIdx.x;            // 512
    const int w    = tid >> 5;               // 0..15
    const int lane = tid & 31;
    const int g    = lane >> 2;              // 0..7
    const int tig  = lane & 3;               // 0..3

    if (tid < HPC) { sA[tid] = g_A1[h * HPC + tid]; sB[tid] = g_B1[h * HPC + tid]; }

    // zero pads: Q/K rows 196..207, V token columns 196..215
    for (int i = tid; i < 12 * 20; i += 512) {
        const int rr = 196 + i / 20, cc = i % 20;
        uQ[rr * 20 + cc] = 0;
        uK[rr * 20 + cc] = 0;
    }
    for (int i = tid; i < 128 * 10; i += 512)
        uV[(i / 10) * 108 + 98 + (i % 10)] = 0;
    __syncthreads();

    // ---- load + BN-normalize + fp16 convert ----
    const size_t base = (size_t)(b * NTOK) * HIDC + h * HPC;
    for (int i = tid; i < NTOK * (HPC / 4); i += 512) {
        const int n  = i / (HPC / 4);
        const int c4 = (i - n * (HPC / 4)) * 4;
        float4 y = *(const float4*)&g_Y[base + (size_t)n * HIDC + c4];
        const float4 a  = *(const float4*)&sA[c4];
        const float4 bb = *(const float4*)&sB[c4];
        y.x = fmaf(y.x, a.x, bb.x);
        y.y = fmaf(y.y, a.y, bb.y);
        y.z = fmaf(y.z, a.z, bb.z);
        y.w = fmaf(y.w, a.w, bb.w);
        if (c4 < KDIM) {
            uQ[n * 20 + c4 / 2]     = pack2(y.x, y.y);
            uQ[n * 20 + c4 / 2 + 1] = pack2(y.z, y.w);
        } else if (c4 < 2 * KDIM) {
            const int cc = c4 - KDIM;
            uK[n * 20 + cc / 2]     = pack2(y.x, y.y);
            uK[n * 20 + cc / 2 + 1] = pack2(y.z, y.w);
        } else {
            const int ch = c4 - 2 * KDIM;
            __half* hv = reinterpret_cast<__half*>(uV);
            hv[(ch + 0) * 216 + n] = __float2half(y.x);
            hv[(ch + 1) * 216 + n] = __float2half(y.y);
            hv[(ch + 2) * 216 + n] = __float2half(y.z);
            hv[(ch + 3) * 216 + n] = __float2half(y.w);
        }
    }
    __syncthreads();

    const int rb = w >> 2;           // 0..3: 16-row block within 64-row tile
    const int ws = w & 3;            // 0..3: work split within phase
    const int r0 = rb * 16;

    const float* biasH = g_bias + (size_t)h * NTOK * NTOK;

    for (int tbase = 0; tbase < NTOK; tbase += 64) {
        const int tcount = (NTOK - tbase < 64) ? (NTOK - tbase) : 64;

        // ---- QK^T + scale + bias -> S (fp32) ----
        if (r0 < tcount) {
            const int rowg = tbase + r0 + g;
            unsigned aq0 = uQ[rowg * 20 + tig];
            unsigned aq1 = uQ[(rowg + 8) * 20 + tig];
            unsigned aq2 = uQ[rowg * 20 + tig + 4];
            unsigned aq3 = uQ[(rowg + 8) * 20 + tig + 4];
            unsigned aq4 = uQ[rowg * 20 + 8 + tig];
            unsigned aq5 = uQ[(rowg + 8) * 20 + 8 + tig];
            unsigned aq6 = uQ[rowg * 20 + 8 + tig + 4];
            unsigned aq7 = uQ[(rowg + 8) * 20 + 8 + tig + 4];

            const int rA = r0 + g, rB = r0 + g + 8;
            const float* bRA = biasH + (size_t)(tbase + rA) * NTOK;
            const float* bRB = biasH + (size_t)(tbase + rB) * NTOK;
            for (int j = ws; j < 26; j += 4) {
                const int tok = 8 * j + g;
                const unsigned b00 = uK[tok * 20 + tig];
                const unsigned b01 = uK[tok * 20 + tig + 4];
                const unsigned b10 = uK[tok * 20 + 8 + tig];
                const unsigned b11 = uK[tok * 20 + 8 + tig + 4];
                float c0 = 0.f, c1 = 0.f, c2 = 0.f, c3 = 0.f;
                mma_f16(c0, c1, c2, c3, aq0, aq1, aq2, aq3, b00, b01);
                mma_f16(c0, c1, c2, c3, aq4, aq5, aq6, aq7, b10, b11);
                const int col0 = 8 * j + 2 * tig;
                if (col0 < NTOK) {   // NTOK even -> col0 < NTOK implies col0+1 < NTOK
                    if (rA < tcount) {
                        const float2 bv = *(const float2*)&bRA[col0];
                        float2 sv = {fmaf(c0, SCALEV, bv.x), fmaf(c1, SCALEV, bv.y)};
                        *(float2*)&S[rA * 212 + col0] = sv;
                    }
                    if (rB < tcount) {
                        const float2 bv = *(const float2*)&bRB[col0];
                        float2 sv = {fmaf(c2, SCALEV, bv.x), fmaf(c3, SCALEV, bv.y)};
                        *(float2*)&S[rB * 212 + col0] = sv;
                    }
                }
            }
        }
        __syncthreads();

        // ---- softmax rows (fp32) -> Ph (fp16, normalized, zero-padded) ----
        for (int rl = w; rl < tcount; rl += 16) {
            float* Sp = S + rl * 212;
            float m = -1e30f;
            for (int j = lane; j < NTOK; j += 32) m = fmaxf(m, Sp[j]);
#pragma unroll
            for (int o = 16; o; o >>= 1) m = fmaxf(m, __shfl_xor_sync(0xffffffffu, m, o));
            float sum = 0.f;
            for (int j = lane; j < NTOK; j += 32) {
                const float e = __expf(Sp[j] - m);
                Sp[j] = e;
                sum += e;
            }
#pragma unroll
            for (int o = 16; o; o >>= 1) sum += __shfl_xor_sync(0xffffffffu, sum, o);
            const float inv = 1.0f / sum;
            for (int jj = lane; jj < 108; jj += 32) {
                const int ca = 2 * jj, cb = 2 * jj + 1;
                const float v0 = (ca < NTOK) ? Sp[ca] * inv : 0.f;
                const float v1 = (cb < NTOK) ? Sp[cb] * inv : 0.f;
                uP[rl * 108 + jj] = pack2(v0, v1);
            }
        }
        __syncthreads();

        // ---- PV (fp16 mma) + hswish -> g_O ----
        if (r0 < tcount) {
            float acc[4][4] = {};
#pragma unroll
            for (int ks = 0; ks < 13; ++ks) {
                const int ko = 8 * ks;
                const unsigned pa0 = uP[(r0 + g) * 108 + ko + tig];
                const unsigned pa1 = uP[(r0 + g + 8) * 108 + ko + tig];
                const unsigned pa2 = uP[(r0 + g) * 108 + ko + tig + 4];
                const unsigned pa3 = uP[(r0 + g + 8) * 108 + ko + tig + 4];
#pragma unroll
                for (int nj = 0; nj < 4; ++nj) {
                    const int ch = ws * 32 + 8 * nj + g;
                    const unsigned vb0 = uV[ch * 108 + ko + tig];
                    const unsigned vb1 = uV[ch * 108 + ko + tig + 4];
                    mma_f16(acc[nj][0], acc[nj][1], acc[nj][2], acc[nj][3],
                            pa0, pa1, pa2, pa3, vb0, vb1);
                }
            }
            const int rA = r0 + g, rB = r0 + g + 8;
#pragma unroll
            for (int nj = 0; nj < 4; ++nj) {
                const int col = h * VDIM + ws * 32 + 8 * nj + 2 * tig;
                if (rA < tcount) {
                    float2 v = {hswish(acc[nj][0]), hswish(acc[nj][1])};
                    *(float2*)&g_O[(size_t)(b * NTOK + tbase + rA) * DHC + col] = v;
                }
                if (rB < tcount) {
                    float2 v = {hswish(acc[nj][2]), hswish(acc[nj][3])};
                    *(float2*)&g_O[(size_t)(b * NTOK + tbase + rB) * DHC + col] = v;
                }
            }
        }
        __syncthreads();
    }
}

// ---------------- final BN apply (in place on d_out) ----------------------------
__global__ void norm2_kernel(float* __restrict__ Z)
{
    const size_t i = (size_t)blockIdx.x * 256 + threadIdx.x;
    float4 z = ((float4*)Z)[i];
    const int c4 = (int)(i & (DIMC / 4 - 1));
    const float4 a  = ((const float4*)g_A2)[c4];
    const float4 bb = ((const float4*)g_B2)[c4];
    z.x = fmaf(z.x, a.x, bb.x);
    z.y = fmaf(z.y, a.y, bb.y);
    z.z = fmaf(z.z, a.z, bb.z);
    z.w = fmaf(z.w, a.w, bb.w);
    ((float4*)Z)[i] = z;
}

// ---------------- launch ---------------------------------------------------------
extern "C" void kernel_launch(void* const* d_in, const int* in_sizes, int n_in,
                              void* d_out, int out_size)
{
    const float* x          = (const float*)d_in[0];
    const float* Wqkv       = (const float*)d_in[1];
    const float* g1         = (const float*)d_in[2];
    const float* b1         = (const float*)d_in[3];
    const float* bias_table = (const float*)d_in[4];
    const float* Wproj      = (const float*)d_in[5];
    const float* g2         = (const float*)d_in[6];
    const float* b2         = (const float*)d_in[7];
    const int*   idxs       = (const int*)d_in[8];
    float*       out        = (float*)d_out;

    float *Y, *O;
    cudaGetSymbolAddress((void**)&Y, g_Y);
    cudaGetSymbolAddress((void**)&O, g_O);

    const size_t attn_smem = (size_t)AOFF_TOT * sizeof(float);
    cudaFuncSetAttribute(attn_kernel, cudaFuncAttributeMaxDynamicSharedMemorySize,
                         (int)attn_smem);

    // 0) expand relative-position bias to full [H,N,N] (L2-resident)
    bias_expand<<<(NHEAD * NTOK * NTOK + 511) / 512, 512>>>(bias_table, idxs);
    // 1) h = x @ Wqkv^T  (fp16 tensor cores, fp32 accum)
    gemm_f16<<<dim3(HIDC / 128, MROWS / 128), 256>>>(x, Wqkv, Y, MROWS, HIDC, DIMC);
    // 2) BN1 stats -> affine
    stats_partial<<<dim3(HIDC / 128, 64), 128>>>(Y, HIDC);
    stats_finalize<<<6, 256>>>(g1, b1, HIDC, 0);
    // 3) attention + hardswish (fp16 tensor cores)
    attn_kernel<<<dim3(BATCHN, NHEAD), 512, attn_smem>>>(nullptr);
    // 4) Z = o @ Wproj^T  (fp16 tensor cores, into d_out)
    gemm_f16<<<dim3(DIMC / 128, MROWS / 128), 256>>>(O, Wproj, out, MROWS, DIMC, DHC);
    // 5) BN2 stats -> affine
    stats_partial<<<dim3(DIMC / 128, 64), 128>>>(out, DIMC);
    stats_finalize<<<1, 256>>>(g2, b2, DIMC, 1);
    // 6) apply BN2 in place
    norm2_kernel<<<(MROWS * DIMC / 4) / 256, 256>>>(out);
}